// round 8
// baseline (speedup 1.0000x reference)
#include <cuda_runtime.h>
#include <cuda_bf16.h>
#include <math.h>

#define SEQ   2048
#define HDIM  512
#define NH    6
#define VOCAB 32000
#define G3    1536          // 3*HDIM
#define GRU_NCTA 32         // 32 CTAs x 512 threads; warp owns one h-element

// ---------------- scratch (device globals; no allocations allowed) -------------
__device__ float g_x   [SEQ*HDIM];                 // embeddings
__device__ float g_q   [NH*SEQ*HDIM];
__device__ float g_k   [NH*SEQ*HDIM];
__device__ float g_v   [NH*SEQ*HDIM];
__device__ float g_sc  [(size_t)NH*SEQ*SEQ];       // attention scores / probs
__device__ float g_cat [SEQ*NH*HDIM];              // concatenated heads (s, h*512+e)
__device__ float g_mha [SEQ*HDIM];
__device__ float g_xln [SEQ*HDIM];                 // post-LN sequence (GRU input)
__device__ float g_gi  [SEQ*G3];                   // x @ W_ih^T + b_ih, all timesteps
__device__ unsigned long long g_ht[2][HDIM];       // tagged hidden: (tag<<32)|f32bits
__device__ float g_logits[VOCAB];
__device__ float g_lse;

// STRONG (morally strong -> single-copy atomic per PTX model) 64-bit ops.
__device__ __forceinline__ unsigned long long ld_acq_u64(const unsigned long long* p){
    unsigned long long v;
    asm volatile("ld.acquire.gpu.global.u64 %0, [%1];" : "=l"(v) : "l"(p) : "memory");
    return v;
}
__device__ __forceinline__ void st_rel_u64(unsigned long long* p, unsigned long long v){
    asm volatile("st.release.gpu.global.u64 [%0], %1;" :: "l"(p), "l"(v) : "memory");
}
__device__ __forceinline__ float tanh_fast(float x){
    float y; asm("tanh.approx.f32 %0, %1;" : "=f"(y) : "f"(x)); return y;
}

// ---------------- embedding gather ---------------------------------------------
__global__ void embed_kernel(const int* __restrict__ tok,
                             const float* __restrict__ emb)
{
    int s = blockIdx.x;
    long long t = tok[s];
    const float4* src = (const float4*)(emb + t*HDIM);
    float4* dst = (float4*)(g_x + (long long)s*HDIM);
    int i = threadIdx.x;               // 128 threads, 128 float4 = 512 floats
    dst[i] = src[i];
}

// ---------------- fp32 tiled GEMM: C = alpha*(A@B[^T]) + bias[col] -------------
// R6 version (known-good, at the fp32 SIMT wall): BM=128, BN=64, BK=16,
// 256 threads, 8x4 microtile, double-buffered smem, 2 CTAs/SM.
template<bool TRANS_B>
__global__ void __launch_bounds__(256, 2)
gemm128(const float* __restrict__ A, const float* __restrict__ B,
        const float* __restrict__ bias, float* __restrict__ C,
        int M, int N, int K, int lda, int ldb, int ldc,
        long long sA, long long sB, long long sC, long long sBias,
        float alpha)
{
    __shared__ float As[2][16][132];
    __shared__ float Bs[2][16][68];
    A += (long long)blockIdx.z * sA;
    B += (long long)blockIdx.z * sB;
    C += (long long)blockIdx.z * sC;
    const float* bi = bias ? (bias + (long long)blockIdx.z * sBias) : (const float*)0;

    const int bm = blockIdx.y * 128;
    const int bn = blockIdx.x * 64;
    const int tid = threadIdx.x;
    const int tx = tid & 15, ty = tid >> 4;        // col group (x4), row group (x8)

    float acc[8][4];
    #pragma unroll
    for (int i = 0; i < 8; i++)
        #pragma unroll
        for (int j = 0; j < 4; j++) acc[i][j] = 0.0f;

    float ra[8], rb[4];

    // prologue: tile 0 -> regs -> buffer 0
    #pragma unroll
    for (int i = 0; i < 8; i++) {
        int idx = tid + i*256;
        int m = idx >> 4, k = idx & 15;
        ra[i] = A[(long long)(bm+m)*lda + k];
    }
    #pragma unroll
    for (int i = 0; i < 4; i++) {
        int idx = tid + i*256;
        if (TRANS_B) { int n = idx >> 4, k = idx & 15; rb[i] = B[(long long)(bn+n)*ldb + k]; }
        else         { int k = idx >> 6, n = idx & 63; rb[i] = B[(long long)k*ldb + (bn+n)]; }
    }
    #pragma unroll
    for (int i = 0; i < 8; i++) {
        int idx = tid + i*256;
        int m = idx >> 4, k = idx & 15;
        As[0][k][m] = ra[i];
    }
    #pragma unroll
    for (int i = 0; i < 4; i++) {
        int idx = tid + i*256;
        if (TRANS_B) { int n = idx >> 4, k = idx & 15; Bs[0][k][n] = rb[i]; }
        else         { int k = idx >> 6, n = idx & 63; Bs[0][k][n] = rb[i]; }
    }
    __syncthreads();

    int cur = 0;
    for (int k0 = 0; k0 < K; k0 += 16) {
        const bool has_next = (k0 + 16 < K);
        if (has_next) {
            const int kn = k0 + 16;
            #pragma unroll
            for (int i = 0; i < 8; i++) {
                int idx = tid + i*256;
                int m = idx >> 4, k = idx & 15;
                ra[i] = A[(long long)(bm+m)*lda + (kn+k)];
            }
            #pragma unroll
            for (int i = 0; i < 4; i++) {
                int idx = tid + i*256;
                if (TRANS_B) { int n = idx >> 4, k = idx & 15; rb[i] = B[(long long)(bn+n)*ldb + (kn+k)]; }
                else         { int k = idx >> 6, n = idx & 63; rb[i] = B[(long long)(kn+k)*ldb + (bn+n)]; }
            }
        }
        #pragma unroll
        for (int kk = 0; kk < 16; kk++) {
            float4 a0 = *(const float4*)&As[cur][kk][ty*8];
            float4 a1 = *(const float4*)&As[cur][kk][ty*8+4];
            float4 b0 = *(const float4*)&Bs[cur][kk][tx*4];
            float af[8] = {a0.x,a0.y,a0.z,a0.w,a1.x,a1.y,a1.z,a1.w};
            float bf[4] = {b0.x,b0.y,b0.z,b0.w};
            #pragma unroll
            for (int i = 0; i < 8; i++)
                #pragma unroll
                for (int j = 0; j < 4; j++)
                    acc[i][j] += af[i]*bf[j];
        }
        if (has_next) {
            const int nxt = cur ^ 1;
            #pragma unroll
            for (int i = 0; i < 8; i++) {
                int idx = tid + i*256;
                int m = idx >> 4, k = idx & 15;
                As[nxt][k][m] = ra[i];
            }
            #pragma unroll
            for (int i = 0; i < 4; i++) {
                int idx = tid + i*256;
                if (TRANS_B) { int n = idx >> 4, k = idx & 15; Bs[nxt][k][n] = rb[i]; }
                else         { int k = idx >> 6, n = idx & 63; Bs[nxt][k][n] = rb[i]; }
            }
            __syncthreads();
            cur = nxt;
        }
    }
    #pragma unroll
    for (int i = 0; i < 8; i++) {
        int row = bm + ty*8 + i;
        float* cp = C + (long long)row*ldc + bn + tx*4;
        #pragma unroll
        for (int j = 0; j < 4; j++) {
            float vv = alpha*acc[i][j];
            if (bi) vv += bi[bn + tx*4 + j];
            cp[j] = vv;
        }
    }
}

// ---------------- row softmax over length-2048 rows ----------------------------
__global__ void softmax2048(float* __restrict__ S)
{
    __shared__ float red[32];
    float* row = S + (long long)blockIdx.x * 2048;
    int tid = threadIdx.x;                         // 256
    float v[8];
    float m = -1e30f;
    #pragma unroll
    for (int i = 0; i < 8; i++) { v[i] = row[tid + i*256]; m = fmaxf(m, v[i]); }
    #pragma unroll
    for (int o = 16; o > 0; o >>= 1) m = fmaxf(m, __shfl_xor_sync(~0u, m, o));
    if ((tid & 31) == 0) red[tid >> 5] = m;
    __syncthreads();
    if (tid == 0) {
        float x = red[0];
        #pragma unroll
        for (int i = 1; i < 8; i++) x = fmaxf(x, red[i]);
        red[0] = x;
    }
    __syncthreads();
    m = red[0];
    __syncthreads();
    float s = 0.0f;
    #pragma unroll
    for (int i = 0; i < 8; i++) { v[i] = __expf(v[i] - m); s += v[i]; }
    #pragma unroll
    for (int o = 16; o > 0; o >>= 1) s += __shfl_xor_sync(~0u, s, o);
    if ((tid & 31) == 0) red[tid >> 5] = s;
    __syncthreads();
    if (tid == 0) {
        float x = 0.0f;
        #pragma unroll
        for (int i = 0; i < 8; i++) x += red[i];
        red[0] = x;
    }
    __syncthreads();
    float inv = 1.0f / red[0];
    #pragma unroll
    for (int i = 0; i < 8; i++) row[tid + i*256] = v[i]*inv;
}

// ---------------- residual + LayerNorm -----------------------------------------
__global__ void resid_ln(const float* __restrict__ gamma, const float* __restrict__ beta)
{
    __shared__ float r1[8], r2[8];
    int s = blockIdx.x, tid = threadIdx.x;         // 256 threads
    const float* xr = g_x   + (long long)s*HDIM;
    const float* mr = g_mha + (long long)s*HDIM;
    float y0 = xr[tid]       + mr[tid];
    float y1 = xr[tid + 256] + mr[tid + 256];
    float sum = y0 + y1, sq = y0*y0 + y1*y1;
    #pragma unroll
    for (int o = 16; o > 0; o >>= 1) {
        sum += __shfl_xor_sync(~0u, sum, o);
        sq  += __shfl_xor_sync(~0u, sq,  o);
    }
    if ((tid & 31) == 0) { r1[tid >> 5] = sum; r2[tid >> 5] = sq; }
    __syncthreads();
    if (tid == 0) {
        float a = 0.0f, b = 0.0f;
        #pragma unroll
        for (int i = 0; i < 8; i++) { a += r1[i]; b += r2[i]; }
        r1[0] = a; r2[0] = b;
    }
    __syncthreads();
    float mu  = r1[0]*(1.0f/512.0f);
    float var = r2[0]*(1.0f/512.0f) - mu*mu;
    float rstd = rsqrtf(var + 1e-5f);
    g_xln[(long long)s*HDIM + tid]       = (y0 - mu)*rstd*gamma[tid]       + beta[tid];
    g_xln[(long long)s*HDIM + 256 + tid] = (y1 - mu)*rstd*gamma[tid + 256] + beta[tid + 256];
}

// ---------------- GRU init: seed h with tag=1, clear stale tags (graph replay!) -
__global__ void gru_init(const float* __restrict__ dec_hid)
{
    int i = threadIdx.x;                           // 512
    g_ht[0][i] = (1ULL << 32) | (unsigned long long)__float_as_uint(dec_hid[i]);
    g_ht[1][i] = 0ULL;                             // stale-tag clear
}

// ---------------- persistent sequential GRU (tag-in-word dataflow sync) --------
// 32 CTAs x 512 threads. Warp w of CTA c owns h-element jj = c*16+w and its
// three gate rows. Each thread polls exactly ONE tag slot (single dependent
// retry chain vs two in R6) and 16 warps/SM hide the L2 discovery latency.
// Strong acquire/release 64-bit tag|value words (single-copy atomic).
__global__ void __launch_bounds__(512)
gru_kernel(const float* __restrict__ W_hh, const float* __restrict__ b_hh)
{
    __shared__ float hs[2][HDIM];
    const int tid = threadIdx.x;                   // 0..511
    const int warp = tid >> 5, lane = tid & 31;
    const int jj = blockIdx.x * 16 + warp;         // 0..511

    float wr0[16], wr1[16], wr2[16];
    const float* w0 = W_hh + (long long)(jj        )*HDIM + lane;
    const float* w1 = W_hh + (long long)(jj +  512 )*HDIM + lane;
    const float* w2 = W_hh + (long long)(jj + 1024 )*HDIM + lane;
    #pragma unroll
    for (int i = 0; i < 16; i++) { wr0[i] = w0[32*i]; wr1[i] = w1[32*i]; wr2[i] = w2[32*i]; }
    const float bh0 = b_hh[jj], bh1 = b_hh[jj + 512], bh2 = b_hh[jj + 1024];

    for (int t = 0; t < SEQ; t++) {
        // prefetch gi for this step (uniform address across the warp -> broadcast)
        float gr = __ldcg(&g_gi[(long long)t*G3 + jj]);
        float gz = __ldcg(&g_gi[(long long)t*G3 + jj + 512]);
        float gn = __ldcg(&g_gi[(long long)t*G3 + jj + 1024]);

        // poll: ONE slot per thread (CTA's 512 threads cover all 512 slots)
        const unsigned long long* hb = g_ht[t & 1];
        const unsigned expect = (unsigned)(t + 1);
        unsigned long long v0 = ld_acq_u64(&hb[tid]);
        while ((unsigned)(v0 >> 32) != expect) v0 = ld_acq_u64(&hb[tid]);

        float* hcur = hs[t & 1];
        hcur[tid] = __uint_as_float((unsigned)v0);
        __syncthreads();

        float hprev = hcur[jj];
        float a0 = 0.0f, a1 = 0.0f, a2 = 0.0f;
        #pragma unroll
        for (int i = 0; i < 16; i++) {
            float h = hcur[lane + 32*i];
            a0 += h*wr0[i];
            a1 += h*wr1[i];
            a2 += h*wr2[i];
        }
        #pragma unroll
        for (int o = 16; o > 0; o >>= 1) {
            a0 += __shfl_xor_sync(~0u, a0, o);
            a1 += __shfl_xor_sync(~0u, a1, o);
            a2 += __shfl_xor_sync(~0u, a2, o);
        }

        if (lane == 0) {
            float r = 0.5f + 0.5f*tanh_fast(0.5f*(gr + a0 + bh0));
            float z = 0.5f + 0.5f*tanh_fast(0.5f*(gz + a1 + bh1));
            float n = tanh_fast(gn + r*(a2 + bh2));
            float hnew = fmaf(z, hprev - n, n);    // (1-z)*n + z*h
            unsigned long long w = ((unsigned long long)(unsigned)(t + 2) << 32)
                                 | (unsigned long long)__float_as_uint(hnew);
            st_rel_u64(&g_ht[(t + 1) & 1][jj], w);
        }
        // no trailing barrier: hs is double-buffered; overwrite of hs[b] occurs at
        // step t+2 whose poll is gated on tags that prove every warp published t+1,
        // and each publish data-depends on that warp's completed reads of hs[b].
    }
}

// ---------------- final projection: logits = h @ W_out + b_out -----------------
// final h (t=2048, tag 2049) lives in g_ht[0] low words
__global__ void logits_kernel(const float* __restrict__ W_out,
                              const float* __restrict__ b_out)
{
    __shared__ float hsm[HDIM];
    for (int i = threadIdx.x; i < HDIM; i += 256)
        hsm[i] = __uint_as_float((unsigned)g_ht[0][i]);
    __syncthreads();
    int v = blockIdx.x*256 + threadIdx.x;
    if (v >= VOCAB) return;
    float acc = b_out[v];
    #pragma unroll 4
    for (int d = 0; d < HDIM; d++) acc += hsm[d]*W_out[(long long)d*VOCAB + v];
    g_logits[v] = acc;
}

__global__ void lse_kernel()
{
    __shared__ float red[32];
    int tid = threadIdx.x;                         // 1024
    float m = -1e30f;
    for (int i = tid; i < VOCAB; i += 1024) m = fmaxf(m, g_logits[i]);
    #pragma unroll
    for (int o = 16; o > 0; o >>= 1) m = fmaxf(m, __shfl_xor_sync(~0u, m, o));
    if ((tid & 31) == 0) red[tid >> 5] = m;
    __syncthreads();
    if (tid == 0) {
        float x = red[0];
        #pragma unroll
        for (int i = 1; i < 32; i++) x = fmaxf(x, red[i]);
        red[0] = x;
    }
    __syncthreads();
    m = red[0];
    __syncthreads();
    float s = 0.0f;
    for (int i = tid; i < VOCAB; i += 1024) s += expf(g_logits[i] - m);
    #pragma unroll
    for (int o = 16; o > 0; o >>= 1) s += __shfl_xor_sync(~0u, s, o);
    if ((tid & 31) == 0) red[tid >> 5] = s;
    __syncthreads();
    if (tid == 0) {
        float x = 0.0f;
        #pragma unroll
        for (int i = 0; i < 32; i++) x += red[i];
        g_lse = m + logf(x);
    }
}

__global__ void out_kernel(float* __restrict__ out)
{
    int i = blockIdx.x*256 + threadIdx.x;
    if (i < VOCAB)            out[i] = g_logits[i] - g_lse;
    else if (i < VOCAB+HDIM)  out[i] = __uint_as_float((unsigned)g_ht[0][i - VOCAB]);
}

// ================================ host side =====================================
extern "C" void kernel_launch(void* const* d_in, const int* in_sizes, int n_in,
                              void* d_out, int out_size)
{
    const int*   tok     = (const int*)  d_in[0];
    const float* dec_hid = (const float*)d_in[1];
    const float* emb     = (const float*)d_in[2];
    const float* Wq      = (const float*)d_in[3];
    const float* bq      = (const float*)d_in[4];
    const float* Wk      = (const float*)d_in[5];
    const float* bk      = (const float*)d_in[6];
    const float* Wv      = (const float*)d_in[7];
    const float* bv      = (const float*)d_in[8];
    const float* Wo      = (const float*)d_in[9];
    const float* bo      = (const float*)d_in[10];
    const float* gamma   = (const float*)d_in[11];
    const float* beta    = (const float*)d_in[12];
    const float* W_ih    = (const float*)d_in[13];
    const float* W_hh    = (const float*)d_in[14];
    const float* b_ih    = (const float*)d_in[15];
    const float* b_hh    = (const float*)d_in[16];
    const float* W_out   = (const float*)d_in[17];
    const float* b_out   = (const float*)d_in[18];
    float* out = (float*)d_out;

    float *px, *pq, *pk, *pV, *psc, *pcat, *pmha, *pxln, *pgi;
    cudaGetSymbolAddress((void**)&px,   g_x);
    cudaGetSymbolAddress((void**)&pq,   g_q);
    cudaGetSymbolAddress((void**)&pk,   g_k);
    cudaGetSymbolAddress((void**)&pV,   g_v);
    cudaGetSymbolAddress((void**)&psc,  g_sc);
    cudaGetSymbolAddress((void**)&pcat, g_cat);
    cudaGetSymbolAddress((void**)&pmha, g_mha);
    cudaGetSymbolAddress((void**)&pxln, g_xln);
    cudaGetSymbolAddress((void**)&pgi,  g_gi);

    // 1) embedding gather
    embed_kernel<<<SEQ, 128>>>(tok, emb);

    // 2) Q/K/V projections: (2048x512)@(512x512) per head, batched over heads
    gemm128<false><<<dim3(8,16,NH), 256>>>(px, Wq, bq, pq, SEQ, HDIM, HDIM,
        HDIM, HDIM, HDIM, 0LL, (long long)HDIM*HDIM, (long long)SEQ*HDIM, HDIM, 1.0f);
    gemm128<false><<<dim3(8,16,NH), 256>>>(px, Wk, bk, pk, SEQ, HDIM, HDIM,
        HDIM, HDIM, HDIM, 0LL, (long long)HDIM*HDIM, (long long)SEQ*HDIM, HDIM, 1.0f);
    gemm128<false><<<dim3(8,16,NH), 256>>>(px, Wv, bv, pV, SEQ, HDIM, HDIM,
        HDIM, HDIM, HDIM, 0LL, (long long)HDIM*HDIM, (long long)SEQ*HDIM, HDIM, 1.0f);

    // 3) scores = Q @ K^T / sqrt(H)
    gemm128<true><<<dim3(32,16,NH), 256>>>(pq, pk, (const float*)0, psc,
        SEQ, SEQ, HDIM, HDIM, HDIM, SEQ,
        (long long)SEQ*HDIM, (long long)SEQ*HDIM, (long long)SEQ*SEQ, 0LL,
        0.04419417382415922f);

    // 4) softmax over last dim
    softmax2048<<<NH*SEQ, 256>>>(psc);

    // 5) heads = P @ V, written directly into concat layout (col offset h*512)
    gemm128<false><<<dim3(8,16,NH), 256>>>(psc, pV, (const float*)0, pcat,
        SEQ, HDIM, SEQ, SEQ, HDIM, NH*HDIM,
        (long long)SEQ*SEQ, (long long)SEQ*HDIM, (long long)HDIM, 0LL, 1.0f);

    // 6) mha = cat @ Wo + bo
    gemm128<false><<<dim3(8,16,1), 256>>>(pcat, Wo, bo, pmha,
        SEQ, HDIM, NH*HDIM, NH*HDIM, HDIM, HDIM, 0LL, 0LL, 0LL, 0LL, 1.0f);

    // 7) residual + layernorm
    resid_ln<<<SEQ, 256>>>(gamma, beta);

    // 8) gi = xln @ W_ih^T + b_ih (all timesteps, parallel)
    gemm128<true><<<dim3(24,16,1), 256>>>(pxln, W_ih, b_ih, pgi,
        SEQ, G3, HDIM, HDIM, HDIM, G3, 0LL, 0LL, 0LL, 0LL, 1.0f);

    // 9) sequential GRU (persistent, register-resident W_hh, tag-word dataflow)
    gru_init<<<1, 512>>>(dec_hid);
    gru_kernel<<<GRU_NCTA, 512>>>(W_hh, b_hh);

    // 10) logits + log_softmax + outputs
    logits_kernel<<<(VOCAB+255)/256, 256>>>(W_out, b_out);
    lse_kernel<<<1, 1024>>>();
    out_kernel<<<(VOCAB+HDIM+255)/256, 256>>>(out);
}

// round 9
// speedup vs baseline: 1.0489x; 1.0489x over previous
#include <cuda_runtime.h>
#include <cuda_bf16.h>
#include <math.h>

#define SEQ   2048
#define HDIM  512
#define NH    6
#define VOCAB 32000
#define G3    1536          // 3*HDIM
#define GRU_NCTA 128        // 128 CTAs x 128 threads; warp owns one h-element

// ---------------- scratch (device globals; no allocations allowed) -------------
__device__ float g_x   [SEQ*HDIM];                 // embeddings
__device__ float g_q   [NH*SEQ*HDIM];
__device__ float g_k   [NH*SEQ*HDIM];
__device__ float g_v   [NH*SEQ*HDIM];
__device__ float g_sc  [(size_t)NH*SEQ*SEQ];       // attention scores / probs
__device__ float g_cat [SEQ*NH*HDIM];              // concatenated heads (s, h*512+e)
__device__ float g_mha [SEQ*HDIM];
__device__ float g_xln [SEQ*HDIM];                 // post-LN sequence (GRU input)
__device__ float g_gi  [SEQ*G3];                   // x @ W_ih^T + b_ih, all timesteps
__device__ unsigned long long g_ht[2][HDIM];       // tagged hidden: (tag<<32)|f32bits
__device__ float g_logits[VOCAB];
__device__ float g_lse;

// STRONG (morally strong -> single-copy atomic per PTX model) 64-bit ops.
__device__ __forceinline__ unsigned long long ld_acq_u64(const unsigned long long* p){
    unsigned long long v;
    asm volatile("ld.acquire.gpu.global.u64 %0, [%1];" : "=l"(v) : "l"(p) : "memory");
    return v;
}
__device__ __forceinline__ void st_rel_u64(unsigned long long* p, unsigned long long v){
    asm volatile("st.release.gpu.global.u64 [%0], %1;" :: "l"(p), "l"(v) : "memory");
}
__device__ __forceinline__ float tanh_fast(float x){
    float y; asm("tanh.approx.f32 %0, %1;" : "=f"(y) : "f"(x)); return y;
}

// ---------------- embedding gather ---------------------------------------------
__global__ void embed_kernel(const int* __restrict__ tok,
                             const float* __restrict__ emb)
{
    int s = blockIdx.x;
    long long t = tok[s];
    const float4* src = (const float4*)(emb + t*HDIM);
    float4* dst = (float4*)(g_x + (long long)s*HDIM);
    int i = threadIdx.x;               // 128 threads, 128 float4 = 512 floats
    dst[i] = src[i];
}

// ---------------- fp32 tiled GEMM: C = alpha*(A@B[^T]) + bias[col] -------------
// R6 version (known-good, at the fp32 SIMT wall): BM=128, BN=64, BK=16,
// 256 threads, 8x4 microtile, double-buffered smem, 2 CTAs/SM.
template<bool TRANS_B>
__global__ void __launch_bounds__(256, 2)
gemm128(const float* __restrict__ A, const float* __restrict__ B,
        const float* __restrict__ bias, float* __restrict__ C,
        int M, int N, int K, int lda, int ldb, int ldc,
        long long sA, long long sB, long long sC, long long sBias,
        float alpha)
{
    __shared__ float As[2][16][132];
    __shared__ float Bs[2][16][68];
    A += (long long)blockIdx.z * sA;
    B += (long long)blockIdx.z * sB;
    C += (long long)blockIdx.z * sC;
    const float* bi = bias ? (bias + (long long)blockIdx.z * sBias) : (const float*)0;

    const int bm = blockIdx.y * 128;
    const int bn = blockIdx.x * 64;
    const int tid = threadIdx.x;
    const int tx = tid & 15, ty = tid >> 4;        // col group (x4), row group (x8)

    float acc[8][4];
    #pragma unroll
    for (int i = 0; i < 8; i++)
        #pragma unroll
        for (int j = 0; j < 4; j++) acc[i][j] = 0.0f;

    float ra[8], rb[4];

    // prologue: tile 0 -> regs -> buffer 0
    #pragma unroll
    for (int i = 0; i < 8; i++) {
        int idx = tid + i*256;
        int m = idx >> 4, k = idx & 15;
        ra[i] = A[(long long)(bm+m)*lda + k];
    }
    #pragma unroll
    for (int i = 0; i < 4; i++) {
        int idx = tid + i*256;
        if (TRANS_B) { int n = idx >> 4, k = idx & 15; rb[i] = B[(long long)(bn+n)*ldb + k]; }
        else         { int k = idx >> 6, n = idx & 63; rb[i] = B[(long long)k*ldb + (bn+n)]; }
    }
    #pragma unroll
    for (int i = 0; i < 8; i++) {
        int idx = tid + i*256;
        int m = idx >> 4, k = idx & 15;
        As[0][k][m] = ra[i];
    }
    #pragma unroll
    for (int i = 0; i < 4; i++) {
        int idx = tid + i*256;
        if (TRANS_B) { int n = idx >> 4, k = idx & 15; Bs[0][k][n] = rb[i]; }
        else         { int k = idx >> 6, n = idx & 63; Bs[0][k][n] = rb[i]; }
    }
    __syncthreads();

    int cur = 0;
    for (int k0 = 0; k0 < K; k0 += 16) {
        const bool has_next = (k0 + 16 < K);
        if (has_next) {
            const int kn = k0 + 16;
            #pragma unroll
            for (int i = 0; i < 8; i++) {
                int idx = tid + i*256;
                int m = idx >> 4, k = idx & 15;
                ra[i] = A[(long long)(bm+m)*lda + (kn+k)];
            }
            #pragma unroll
            for (int i = 0; i < 4; i++) {
                int idx = tid + i*256;
                if (TRANS_B) { int n = idx >> 4, k = idx & 15; rb[i] = B[(long long)(bn+n)*ldb + (kn+k)]; }
                else         { int k = idx >> 6, n = idx & 63; rb[i] = B[(long long)(kn+k)*ldb + (bn+n)]; }
            }
        }
        #pragma unroll
        for (int kk = 0; kk < 16; kk++) {
            float4 a0 = *(const float4*)&As[cur][kk][ty*8];
            float4 a1 = *(const float4*)&As[cur][kk][ty*8+4];
            float4 b0 = *(const float4*)&Bs[cur][kk][tx*4];
            float af[8] = {a0.x,a0.y,a0.z,a0.w,a1.x,a1.y,a1.z,a1.w};
            float bf[4] = {b0.x,b0.y,b0.z,b0.w};
            #pragma unroll
            for (int i = 0; i < 8; i++)
                #pragma unroll
                for (int j = 0; j < 4; j++)
                    acc[i][j] += af[i]*bf[j];
        }
        if (has_next) {
            const int nxt = cur ^ 1;
            #pragma unroll
            for (int i = 0; i < 8; i++) {
                int idx = tid + i*256;
                int m = idx >> 4, k = idx & 15;
                As[nxt][k][m] = ra[i];
            }
            #pragma unroll
            for (int i = 0; i < 4; i++) {
                int idx = tid + i*256;
                if (TRANS_B) { int n = idx >> 4, k = idx & 15; Bs[nxt][k][n] = rb[i]; }
                else         { int k = idx >> 6, n = idx & 63; Bs[nxt][k][n] = rb[i]; }
            }
            __syncthreads();
            cur = nxt;
        }
    }
    #pragma unroll
    for (int i = 0; i < 8; i++) {
        int row = bm + ty*8 + i;
        float* cp = C + (long long)row*ldc + bn + tx*4;
        #pragma unroll
        for (int j = 0; j < 4; j++) {
            float vv = alpha*acc[i][j];
            if (bi) vv += bi[bn + tx*4 + j];
            cp[j] = vv;
        }
    }
}

// ---------------- row softmax over length-2048 rows ----------------------------
__global__ void softmax2048(float* __restrict__ S)
{
    __shared__ float red[32];
    float* row = S + (long long)blockIdx.x * 2048;
    int tid = threadIdx.x;                         // 256
    float v[8];
    float m = -1e30f;
    #pragma unroll
    for (int i = 0; i < 8; i++) { v[i] = row[tid + i*256]; m = fmaxf(m, v[i]); }
    #pragma unroll
    for (int o = 16; o > 0; o >>= 1) m = fmaxf(m, __shfl_xor_sync(~0u, m, o));
    if ((tid & 31) == 0) red[tid >> 5] = m;
    __syncthreads();
    if (tid == 0) {
        float x = red[0];
        #pragma unroll
        for (int i = 1; i < 8; i++) x = fmaxf(x, red[i]);
        red[0] = x;
    }
    __syncthreads();
    m = red[0];
    __syncthreads();
    float s = 0.0f;
    #pragma unroll
    for (int i = 0; i < 8; i++) { v[i] = __expf(v[i] - m); s += v[i]; }
    #pragma unroll
    for (int o = 16; o > 0; o >>= 1) s += __shfl_xor_sync(~0u, s, o);
    if ((tid & 31) == 0) red[tid >> 5] = s;
    __syncthreads();
    if (tid == 0) {
        float x = 0.0f;
        #pragma unroll
        for (int i = 0; i < 8; i++) x += red[i];
        red[0] = x;
    }
    __syncthreads();
    float inv = 1.0f / red[0];
    #pragma unroll
    for (int i = 0; i < 8; i++) row[tid + i*256] = v[i]*inv;
}

// ---------------- residual + LayerNorm -----------------------------------------
__global__ void resid_ln(const float* __restrict__ gamma, const float* __restrict__ beta)
{
    __shared__ float r1[8], r2[8];
    int s = blockIdx.x, tid = threadIdx.x;         // 256 threads
    const float* xr = g_x   + (long long)s*HDIM;
    const float* mr = g_mha + (long long)s*HDIM;
    float y0 = xr[tid]       + mr[tid];
    float y1 = xr[tid + 256] + mr[tid + 256];
    float sum = y0 + y1, sq = y0*y0 + y1*y1;
    #pragma unroll
    for (int o = 16; o > 0; o >>= 1) {
        sum += __shfl_xor_sync(~0u, sum, o);
        sq  += __shfl_xor_sync(~0u, sq,  o);
    }
    if ((tid & 31) == 0) { r1[tid >> 5] = sum; r2[tid >> 5] = sq; }
    __syncthreads();
    if (tid == 0) {
        float a = 0.0f, b = 0.0f;
        #pragma unroll
        for (int i = 0; i < 8; i++) { a += r1[i]; b += r2[i]; }
        r1[0] = a; r2[0] = b;
    }
    __syncthreads();
    float mu  = r1[0]*(1.0f/512.0f);
    float var = r2[0]*(1.0f/512.0f) - mu*mu;
    float rstd = rsqrtf(var + 1e-5f);
    g_xln[(long long)s*HDIM + tid]       = (y0 - mu)*rstd*gamma[tid]       + beta[tid];
    g_xln[(long long)s*HDIM + 256 + tid] = (y1 - mu)*rstd*gamma[tid + 256] + beta[tid + 256];
}

// ---------------- GRU init: seed h with tag=1, clear stale tags (graph replay!) -
__global__ void gru_init(const float* __restrict__ dec_hid)
{
    int i = threadIdx.x;                           // 512
    g_ht[0][i] = (1ULL << 32) | (unsigned long long)__float_as_uint(dec_hid[i]);
    g_ht[1][i] = 0ULL;                             // stale-tag clear
}

// ---------------- persistent sequential GRU (tag-in-word dataflow sync) --------
// 128 CTAs x 128 threads. Warp w of CTA c owns h-element jj = c*4+w and its
// three gate rows. During compute each SMSP runs exactly ONE warp (no issue
// sharing) and the CTA barrier couples only 4 warps (minimal skew) — the
// R7/R8 lesson was that wide CTAs / shared SMSPs hurt the 2048x critical path.
// Each thread polls 4 tag slots, all 4 acquires issued before any check.
// Strong acquire/release 64-bit tag|value words (single-copy atomic).
__global__ void __launch_bounds__(128)
gru_kernel(const float* __restrict__ W_hh, const float* __restrict__ b_hh)
{
    __shared__ float hs[2][HDIM];
    const int tid = threadIdx.x;                   // 0..127
    const int warp = tid >> 5, lane = tid & 31;
    const int jj = blockIdx.x * 4 + warp;          // 0..511

    float wr0[16], wr1[16], wr2[16];
    const float* w0 = W_hh + (long long)(jj        )*HDIM + lane;
    const float* w1 = W_hh + (long long)(jj +  512 )*HDIM + lane;
    const float* w2 = W_hh + (long long)(jj + 1024 )*HDIM + lane;
    #pragma unroll
    for (int i = 0; i < 16; i++) { wr0[i] = w0[32*i]; wr1[i] = w1[32*i]; wr2[i] = w2[32*i]; }
    const float bh0 = b_hh[jj], bh1 = b_hh[jj + 512], bh2 = b_hh[jj + 1024];

    for (int t = 0; t < SEQ; t++) {
        // prefetch gi for this step (uniform address across the warp -> broadcast)
        float gr = __ldcg(&g_gi[(long long)t*G3 + jj]);
        float gz = __ldcg(&g_gi[(long long)t*G3 + jj + 512]);
        float gn = __ldcg(&g_gi[(long long)t*G3 + jj + 1024]);

        // poll: 4 slots per thread, all acquires in flight before first check
        const unsigned long long* hb = g_ht[t & 1];
        const unsigned expect = (unsigned)(t + 1);
        unsigned long long v0 = ld_acq_u64(&hb[tid]);
        unsigned long long v1 = ld_acq_u64(&hb[tid + 128]);
        unsigned long long v2 = ld_acq_u64(&hb[tid + 256]);
        unsigned long long v3 = ld_acq_u64(&hb[tid + 384]);
        while ((unsigned)(v0 >> 32) != expect) v0 = ld_acq_u64(&hb[tid]);
        while ((unsigned)(v1 >> 32) != expect) v1 = ld_acq_u64(&hb[tid + 128]);
        while ((unsigned)(v2 >> 32) != expect) v2 = ld_acq_u64(&hb[tid + 256]);
        while ((unsigned)(v3 >> 32) != expect) v3 = ld_acq_u64(&hb[tid + 384]);

        float* hcur = hs[t & 1];
        hcur[tid]       = __uint_as_float((unsigned)v0);
        hcur[tid + 128] = __uint_as_float((unsigned)v1);
        hcur[tid + 256] = __uint_as_float((unsigned)v2);
        hcur[tid + 384] = __uint_as_float((unsigned)v3);
        __syncthreads();

        float hprev = hcur[jj];
        float a0 = 0.0f, a1 = 0.0f, a2 = 0.0f;
        #pragma unroll
        for (int i = 0; i < 16; i++) {
            float h = hcur[lane + 32*i];
            a0 += h*wr0[i];
            a1 += h*wr1[i];
            a2 += h*wr2[i];
        }
        #pragma unroll
        for (int o = 16; o > 0; o >>= 1) {
            a0 += __shfl_xor_sync(~0u, a0, o);
            a1 += __shfl_xor_sync(~0u, a1, o);
            a2 += __shfl_xor_sync(~0u, a2, o);
        }

        if (lane == 0) {
            float r = 0.5f + 0.5f*tanh_fast(0.5f*(gr + a0 + bh0));
            float z = 0.5f + 0.5f*tanh_fast(0.5f*(gz + a1 + bh1));
            float n = tanh_fast(gn + r*(a2 + bh2));
            float hnew = fmaf(z, hprev - n, n);    // (1-z)*n + z*h
            unsigned long long w = ((unsigned long long)(unsigned)(t + 2) << 32)
                                 | (unsigned long long)__float_as_uint(hnew);
            st_rel_u64(&g_ht[(t + 1) & 1][jj], w);
        }
        // no trailing barrier: hs is double-buffered; overwrite of hs[b] occurs at
        // step t+2 whose poll is gated on tags that prove every warp published t+1,
        // and each publish data-depends on that warp's completed reads of hs[b].
    }
}

// ---------------- final projection: logits = h @ W_out + b_out -----------------
// final h (t=2048, tag 2049) lives in g_ht[0] low words
__global__ void logits_kernel(const float* __restrict__ W_out,
                              const float* __restrict__ b_out)
{
    __shared__ float hsm[HDIM];
    for (int i = threadIdx.x; i < HDIM; i += 256)
        hsm[i] = __uint_as_float((unsigned)g_ht[0][i]);
    __syncthreads();
    int v = blockIdx.x*256 + threadIdx.x;
    if (v >= VOCAB) return;
    float acc = b_out[v];
    #pragma unroll 4
    for (int d = 0; d < HDIM; d++) acc += hsm[d]*W_out[(long long)d*VOCAB + v];
    g_logits[v] = acc;
}

__global__ void lse_kernel()
{
    __shared__ float red[32];
    int tid = threadIdx.x;                         // 1024
    float m = -1e30f;
    for (int i = tid; i < VOCAB; i += 1024) m = fmaxf(m, g_logits[i]);
    #pragma unroll
    for (int o = 16; o > 0; o >>= 1) m = fmaxf(m, __shfl_xor_sync(~0u, m, o));
    if ((tid & 31) == 0) red[tid >> 5] = m;
    __syncthreads();
    if (tid == 0) {
        float x = red[0];
        #pragma unroll
        for (int i = 1; i < 32; i++) x = fmaxf(x, red[i]);
        red[0] = x;
    }
    __syncthreads();
    m = red[0];
    __syncthreads();
    float s = 0.0f;
    for (int i = tid; i < VOCAB; i += 1024) s += expf(g_logits[i] - m);
    #pragma unroll
    for (int o = 16; o > 0; o >>= 1) s += __shfl_xor_sync(~0u, s, o);
    if ((tid & 31) == 0) red[tid >> 5] = s;
    __syncthreads();
    if (tid == 0) {
        float x = 0.0f;
        #pragma unroll
        for (int i = 0; i < 32; i++) x += red[i];
        g_lse = m + logf(x);
    }
}

__global__ void out_kernel(float* __restrict__ out)
{
    int i = blockIdx.x*256 + threadIdx.x;
    if (i < VOCAB)            out[i] = g_logits[i] - g_lse;
    else if (i < VOCAB+HDIM)  out[i] = __uint_as_float((unsigned)g_ht[0][i - VOCAB]);
}

// ================================ host side =====================================
extern "C" void kernel_launch(void* const* d_in, const int* in_sizes, int n_in,
                              void* d_out, int out_size)
{
    const int*   tok     = (const int*)  d_in[0];
    const float* dec_hid = (const float*)d_in[1];
    const float* emb     = (const float*)d_in[2];
    const float* Wq      = (const float*)d_in[3];
    const float* bq      = (const float*)d_in[4];
    const float* Wk      = (const float*)d_in[5];
    const float* bk      = (const float*)d_in[6];
    const float* Wv      = (const float*)d_in[7];
    const float* bv      = (const float*)d_in[8];
    const float* Wo      = (const float*)d_in[9];
    const float* bo      = (const float*)d_in[10];
    const float* gamma   = (const float*)d_in[11];
    const float* beta    = (const float*)d_in[12];
    const float* W_ih    = (const float*)d_in[13];
    const float* W_hh    = (const float*)d_in[14];
    const float* b_ih    = (const float*)d_in[15];
    const float* b_hh    = (const float*)d_in[16];
    const float* W_out   = (const float*)d_in[17];
    const float* b_out   = (const float*)d_in[18];
    float* out = (float*)d_out;

    float *px, *pq, *pk, *pV, *psc, *pcat, *pmha, *pxln, *pgi;
    cudaGetSymbolAddress((void**)&px,   g_x);
    cudaGetSymbolAddress((void**)&pq,   g_q);
    cudaGetSymbolAddress((void**)&pk,   g_k);
    cudaGetSymbolAddress((void**)&pV,   g_v);
    cudaGetSymbolAddress((void**)&psc,  g_sc);
    cudaGetSymbolAddress((void**)&pcat, g_cat);
    cudaGetSymbolAddress((void**)&pmha, g_mha);
    cudaGetSymbolAddress((void**)&pxln, g_xln);
    cudaGetSymbolAddress((void**)&pgi,  g_gi);

    // 1) embedding gather
    embed_kernel<<<SEQ, 128>>>(tok, emb);

    // 2) Q/K/V projections: (2048x512)@(512x512) per head, batched over heads
    gemm128<false><<<dim3(8,16,NH), 256>>>(px, Wq, bq, pq, SEQ, HDIM, HDIM,
        HDIM, HDIM, HDIM, 0LL, (long long)HDIM*HDIM, (long long)SEQ*HDIM, HDIM, 1.0f);
    gemm128<false><<<dim3(8,16,NH), 256>>>(px, Wk, bk, pk, SEQ, HDIM, HDIM,
        HDIM, HDIM, HDIM, 0LL, (long long)HDIM*HDIM, (long long)SEQ*HDIM, HDIM, 1.0f);
    gemm128<false><<<dim3(8,16,NH), 256>>>(px, Wv, bv, pV, SEQ, HDIM, HDIM,
        HDIM, HDIM, HDIM, 0LL, (long long)HDIM*HDIM, (long long)SEQ*HDIM, HDIM, 1.0f);

    // 3) scores = Q @ K^T / sqrt(H)
    gemm128<true><<<dim3(32,16,NH), 256>>>(pq, pk, (const float*)0, psc,
        SEQ, SEQ, HDIM, HDIM, HDIM, SEQ,
        (long long)SEQ*HDIM, (long long)SEQ*HDIM, (long long)SEQ*SEQ, 0LL,
        0.04419417382415922f);

    // 4) softmax over last dim
    softmax2048<<<NH*SEQ, 256>>>(psc);

    // 5) heads = P @ V, written directly into concat layout (col offset h*512)
    gemm128<false><<<dim3(8,16,NH), 256>>>(psc, pV, (const float*)0, pcat,
        SEQ, HDIM, SEQ, SEQ, HDIM, NH*HDIM,
        (long long)SEQ*SEQ, (long long)SEQ*HDIM, (long long)HDIM, 0LL, 1.0f);

    // 6) mha = cat @ Wo + bo
    gemm128<false><<<dim3(8,16,1), 256>>>(pcat, Wo, bo, pmha,
        SEQ, HDIM, NH*HDIM, NH*HDIM, HDIM, HDIM, 0LL, 0LL, 0LL, 0LL, 1.0f);

    // 7) residual + layernorm
    resid_ln<<<SEQ, 256>>>(gamma, beta);

    // 8) gi = xln @ W_ih^T + b_ih (all timesteps, parallel)
    gemm128<true><<<dim3(24,16,1), 256>>>(pxln, W_ih, b_ih, pgi,
        SEQ, G3, HDIM, HDIM, HDIM, G3, 0LL, 0LL, 0LL, 0LL, 1.0f);

    // 9) sequential GRU (persistent, register-resident W_hh, tag-word dataflow)
    gru_init<<<1, 512>>>(dec_hid);
    gru_kernel<<<GRU_NCTA, 128>>>(W_hh, b_hh);

    // 10) logits + log_softmax + outputs
    logits_kernel<<<(VOCAB+255)/256, 256>>>(W_out, b_out);
    lse_kernel<<<1, 1024>>>();
    out_kernel<<<(VOCAB+HDIM+255)/256, 256>>>(out);
}

// round 10
// speedup vs baseline: 1.1118x; 1.0600x over previous
#include <cuda_runtime.h>
#include <cuda_bf16.h>
#include <math.h>

#define SEQ   2048
#define HDIM  512
#define NH    6
#define VOCAB 32000
#define G3    1536          // 3*HDIM
#define GRU_NCTA 64         // 64 CTAs x 256 threads (best measured shape)

// ---------------- scratch (device globals; no allocations allowed) -------------
__device__ float g_x   [SEQ*HDIM];                 // embeddings
__device__ float g_q   [NH*SEQ*HDIM];
__device__ float g_k   [NH*SEQ*HDIM];
__device__ float g_v   [NH*SEQ*HDIM];
__device__ float g_sc  [(size_t)NH*SEQ*SEQ];       // attention scores / probs
__device__ float g_cat [SEQ*NH*HDIM];              // concatenated heads (s, h*512+e)
__device__ float g_mha [SEQ*HDIM];
__device__ float g_xln [SEQ*HDIM];                 // post-LN sequence (GRU input)
__device__ float g_gi  [SEQ*G3];                   // x @ W_ih^T + b_ih, all timesteps
__device__ unsigned long long g_ht[2][HDIM];       // tagged hidden: (tag<<32)|f32bits
__device__ float g_logits[VOCAB];
__device__ float g_lse;

// Morally-strong 64-bit ops (single-copy atomic per PTX model; no tearing).
__device__ __forceinline__ unsigned long long ld_rlx_u64(const unsigned long long* p){
    unsigned long long v;
    asm volatile("ld.relaxed.gpu.global.u64 %0, [%1];" : "=l"(v) : "l"(p) : "memory");
    return v;
}
__device__ __forceinline__ void st_rel_u64(unsigned long long* p, unsigned long long v){
    asm volatile("st.release.gpu.global.u64 [%0], %1;" :: "l"(p), "l"(v) : "memory");
}
__device__ __forceinline__ void fence_acq_rel_gpu(){
    asm volatile("fence.acq_rel.gpu;" ::: "memory");
}
__device__ __forceinline__ float tanh_fast(float x){
    float y; asm("tanh.approx.f32 %0, %1;" : "=f"(y) : "f"(x)); return y;
}

// ---------------- embedding gather ---------------------------------------------
__global__ void embed_kernel(const int* __restrict__ tok,
                             const float* __restrict__ emb)
{
    int s = blockIdx.x;
    long long t = tok[s];
    const float4* src = (const float4*)(emb + t*HDIM);
    float4* dst = (float4*)(g_x + (long long)s*HDIM);
    int i = threadIdx.x;               // 128 threads, 128 float4 = 512 floats
    dst[i] = src[i];
}

// ---------------- fp32 tiled GEMM: C = alpha*(A@B[^T]) + bias[col] -------------
// R6 version (known-good, at the fp32 SIMT wall): BM=128, BN=64, BK=16,
// 256 threads, 8x4 microtile, double-buffered smem, 2 CTAs/SM.
template<bool TRANS_B>
__global__ void __launch_bounds__(256, 2)
gemm128(const float* __restrict__ A, const float* __restrict__ B,
        const float* __restrict__ bias, float* __restrict__ C,
        int M, int N, int K, int lda, int ldb, int ldc,
        long long sA, long long sB, long long sC, long long sBias,
        float alpha)
{
    __shared__ float As[2][16][132];
    __shared__ float Bs[2][16][68];
    A += (long long)blockIdx.z * sA;
    B += (long long)blockIdx.z * sB;
    C += (long long)blockIdx.z * sC;
    const float* bi = bias ? (bias + (long long)blockIdx.z * sBias) : (const float*)0;

    const int bm = blockIdx.y * 128;
    const int bn = blockIdx.x * 64;
    const int tid = threadIdx.x;
    const int tx = tid & 15, ty = tid >> 4;        // col group (x4), row group (x8)

    float acc[8][4];
    #pragma unroll
    for (int i = 0; i < 8; i++)
        #pragma unroll
        for (int j = 0; j < 4; j++) acc[i][j] = 0.0f;

    float ra[8], rb[4];

    // prologue: tile 0 -> regs -> buffer 0
    #pragma unroll
    for (int i = 0; i < 8; i++) {
        int idx = tid + i*256;
        int m = idx >> 4, k = idx & 15;
        ra[i] = A[(long long)(bm+m)*lda + k];
    }
    #pragma unroll
    for (int i = 0; i < 4; i++) {
        int idx = tid + i*256;
        if (TRANS_B) { int n = idx >> 4, k = idx & 15; rb[i] = B[(long long)(bn+n)*ldb + k]; }
        else         { int k = idx >> 6, n = idx & 63; rb[i] = B[(long long)k*ldb + (bn+n)]; }
    }
    #pragma unroll
    for (int i = 0; i < 8; i++) {
        int idx = tid + i*256;
        int m = idx >> 4, k = idx & 15;
        As[0][k][m] = ra[i];
    }
    #pragma unroll
    for (int i = 0; i < 4; i++) {
        int idx = tid + i*256;
        if (TRANS_B) { int n = idx >> 4, k = idx & 15; Bs[0][k][n] = rb[i]; }
        else         { int k = idx >> 6, n = idx & 63; Bs[0][k][n] = rb[i]; }
    }
    __syncthreads();

    int cur = 0;
    for (int k0 = 0; k0 < K; k0 += 16) {
        const bool has_next = (k0 + 16 < K);
        if (has_next) {
            const int kn = k0 + 16;
            #pragma unroll
            for (int i = 0; i < 8; i++) {
                int idx = tid + i*256;
                int m = idx >> 4, k = idx & 15;
                ra[i] = A[(long long)(bm+m)*lda + (kn+k)];
            }
            #pragma unroll
            for (int i = 0; i < 4; i++) {
                int idx = tid + i*256;
                if (TRANS_B) { int n = idx >> 4, k = idx & 15; rb[i] = B[(long long)(bn+n)*ldb + (kn+k)]; }
                else         { int k = idx >> 6, n = idx & 63; rb[i] = B[(long long)(kn+k)*ldb + (bn+n)]; }
            }
        }
        #pragma unroll
        for (int kk = 0; kk < 16; kk++) {
            float4 a0 = *(const float4*)&As[cur][kk][ty*8];
            float4 a1 = *(const float4*)&As[cur][kk][ty*8+4];
            float4 b0 = *(const float4*)&Bs[cur][kk][tx*4];
            float af[8] = {a0.x,a0.y,a0.z,a0.w,a1.x,a1.y,a1.z,a1.w};
            float bf[4] = {b0.x,b0.y,b0.z,b0.w};
            #pragma unroll
            for (int i = 0; i < 8; i++)
                #pragma unroll
                for (int j = 0; j < 4; j++)
                    acc[i][j] += af[i]*bf[j];
        }
        if (has_next) {
            const int nxt = cur ^ 1;
            #pragma unroll
            for (int i = 0; i < 8; i++) {
                int idx = tid + i*256;
                int m = idx >> 4, k = idx & 15;
                As[nxt][k][m] = ra[i];
            }
            #pragma unroll
            for (int i = 0; i < 4; i++) {
                int idx = tid + i*256;
                if (TRANS_B) { int n = idx >> 4, k = idx & 15; Bs[nxt][k][n] = rb[i]; }
                else         { int k = idx >> 6, n = idx & 63; Bs[nxt][k][n] = rb[i]; }
            }
            __syncthreads();
            cur = nxt;
        }
    }
    #pragma unroll
    for (int i = 0; i < 8; i++) {
        int row = bm + ty*8 + i;
        float* cp = C + (long long)row*ldc + bn + tx*4;
        #pragma unroll
        for (int j = 0; j < 4; j++) {
            float vv = alpha*acc[i][j];
            if (bi) vv += bi[bn + tx*4 + j];
            cp[j] = vv;
        }
    }
}

// ---------------- row softmax over length-2048 rows ----------------------------
__global__ void softmax2048(float* __restrict__ S)
{
    __shared__ float red[32];
    float* row = S + (long long)blockIdx.x * 2048;
    int tid = threadIdx.x;                         // 256
    float v[8];
    float m = -1e30f;
    #pragma unroll
    for (int i = 0; i < 8; i++) { v[i] = row[tid + i*256]; m = fmaxf(m, v[i]); }
    #pragma unroll
    for (int o = 16; o > 0; o >>= 1) m = fmaxf(m, __shfl_xor_sync(~0u, m, o));
    if ((tid & 31) == 0) red[tid >> 5] = m;
    __syncthreads();
    if (tid == 0) {
        float x = red[0];
        #pragma unroll
        for (int i = 1; i < 8; i++) x = fmaxf(x, red[i]);
        red[0] = x;
    }
    __syncthreads();
    m = red[0];
    __syncthreads();
    float s = 0.0f;
    #pragma unroll
    for (int i = 0; i < 8; i++) { v[i] = __expf(v[i] - m); s += v[i]; }
    #pragma unroll
    for (int o = 16; o > 0; o >>= 1) s += __shfl_xor_sync(~0u, s, o);
    if ((tid & 31) == 0) red[tid >> 5] = s;
    __syncthreads();
    if (tid == 0) {
        float x = 0.0f;
        #pragma unroll
        for (int i = 0; i < 8; i++) x += red[i];
        red[0] = x;
    }
    __syncthreads();
    float inv = 1.0f / red[0];
    #pragma unroll
    for (int i = 0; i < 8; i++) row[tid + i*256] = v[i]*inv;
}

// ---------------- residual + LayerNorm -----------------------------------------
__global__ void resid_ln(const float* __restrict__ gamma, const float* __restrict__ beta)
{
    __shared__ float r1[8], r2[8];
    int s = blockIdx.x, tid = threadIdx.x;         // 256 threads
    const float* xr = g_x   + (long long)s*HDIM;
    const float* mr = g_mha + (long long)s*HDIM;
    float y0 = xr[tid]       + mr[tid];
    float y1 = xr[tid + 256] + mr[tid + 256];
    float sum = y0 + y1, sq = y0*y0 + y1*y1;
    #pragma unroll
    for (int o = 16; o > 0; o >>= 1) {
        sum += __shfl_xor_sync(~0u, sum, o);
        sq  += __shfl_xor_sync(~0u, sq,  o);
    }
    if ((tid & 31) == 0) { r1[tid >> 5] = sum; r2[tid >> 5] = sq; }
    __syncthreads();
    if (tid == 0) {
        float a = 0.0f, b = 0.0f;
        #pragma unroll
        for (int i = 0; i < 8; i++) { a += r1[i]; b += r2[i]; }
        r1[0] = a; r2[0] = b;
    }
    __syncthreads();
    float mu  = r1[0]*(1.0f/512.0f);
    float var = r2[0]*(1.0f/512.0f) - mu*mu;
    float rstd = rsqrtf(var + 1e-5f);
    g_xln[(long long)s*HDIM + tid]       = (y0 - mu)*rstd*gamma[tid]       + beta[tid];
    g_xln[(long long)s*HDIM + 256 + tid] = (y1 - mu)*rstd*gamma[tid + 256] + beta[tid + 256];
}

// ---------------- GRU init: seed h with tag=1, clear stale tags (graph replay!) -
__global__ void gru_init(const float* __restrict__ dec_hid)
{
    int i = threadIdx.x;                           // 512
    g_ht[0][i] = (1ULL << 32) | (unsigned long long)__float_as_uint(dec_hid[i]);
    g_ht[1][i] = 0ULL;                             // stale-tag clear
}

// ---------------- persistent sequential GRU (tag-in-word dataflow sync) --------
// R6 topology (64 CTAs x 256 threads; warp owns h-element jj = cta*8+warp;
// thread polls slots tid and tid+256). New in R10: 2-deep software-pipelined
// RELAXED probes per slot (probe interval ~RT/2 instead of a full dependent
// L2 round trip per retry), followed by ONE fence.acq_rel.gpu that pairs with
// the producers' release stores — restores the happens-before chain that
// makes buffer overwrite safe, at one fence per step instead of acquire
// ordering on every probe. Tag|value words are single-copy atomic (morally
// strong relaxed), so no tearing.
__global__ void gru_kernel(const float* __restrict__ W_hh,
                           const float* __restrict__ b_hh)
{
    __shared__ float hs[2][HDIM];
    const int tid = threadIdx.x;
    const int warp = tid >> 5, lane = tid & 31;
    const int jj = blockIdx.x * 8 + warp;          // 0..511

    float wr0[16], wr1[16], wr2[16];
    const float* w0 = W_hh + (long long)(jj        )*HDIM + lane;
    const float* w1 = W_hh + (long long)(jj +  512 )*HDIM + lane;
    const float* w2 = W_hh + (long long)(jj + 1024 )*HDIM + lane;
    #pragma unroll
    for (int i = 0; i < 16; i++) { wr0[i] = w0[32*i]; wr1[i] = w1[32*i]; wr2[i] = w2[32*i]; }
    const float bh0 = b_hh[jj], bh1 = b_hh[jj + 512], bh2 = b_hh[jj + 1024];

    for (int t = 0; t < SEQ; t++) {
        // prefetch gi for this step (uniform address across the warp -> broadcast)
        float gr = __ldcg(&g_gi[(long long)t*G3 + jj]);
        float gz = __ldcg(&g_gi[(long long)t*G3 + jj + 512]);
        float gn = __ldcg(&g_gi[(long long)t*G3 + jj + 1024]);

        const unsigned long long* hb = g_ht[t & 1];
        const unsigned long long* pa = &hb[tid];
        const unsigned long long* pb = &hb[tid + 256];
        const unsigned expect = (unsigned)(t + 1);

        // 2-deep pipelined probes per slot: two independent loads of the same
        // word in flight, checked alternately -> discovery granularity ~RT/2.
        unsigned long long a0 = ld_rlx_u64(pa);
        unsigned long long b0 = ld_rlx_u64(pb);
        unsigned long long a1 = ld_rlx_u64(pa);
        unsigned long long b1 = ld_rlx_u64(pb);

        unsigned long long va;
        for (;;) {
            if ((unsigned)(a0 >> 32) == expect) { va = a0; break; }
            a0 = ld_rlx_u64(pa);
            if ((unsigned)(a1 >> 32) == expect) { va = a1; break; }
            a1 = ld_rlx_u64(pa);
        }
        unsigned long long vb;
        for (;;) {
            if ((unsigned)(b0 >> 32) == expect) { vb = b0; break; }
            b0 = ld_rlx_u64(pb);
            if ((unsigned)(b1 >> 32) == expect) { vb = b1; break; }
            b1 = ld_rlx_u64(pb);
        }
        // pair the relaxed tag observations with producers' release stores
        fence_acq_rel_gpu();

        float* hcur = hs[t & 1];
        hcur[tid]       = __uint_as_float((unsigned)va);
        hcur[tid + 256] = __uint_as_float((unsigned)vb);
        __syncthreads();

        float hprev = hcur[jj];
        float a0f = 0.0f, a1f = 0.0f, a2f = 0.0f;
        #pragma unroll
        for (int i = 0; i < 16; i++) {
            float h = hcur[lane + 32*i];
            a0f += h*wr0[i];
            a1f += h*wr1[i];
            a2f += h*wr2[i];
        }
        #pragma unroll
        for (int o = 16; o > 0; o >>= 1) {
            a0f += __shfl_xor_sync(~0u, a0f, o);
            a1f += __shfl_xor_sync(~0u, a1f, o);
            a2f += __shfl_xor_sync(~0u, a2f, o);
        }

        if (lane == 0) {
            float r = 0.5f + 0.5f*tanh_fast(0.5f*(gr + a0f + bh0));
            float z = 0.5f + 0.5f*tanh_fast(0.5f*(gz + a1f + bh1));
            float n = tanh_fast(gn + r*(a2f + bh2));
            float hnew = fmaf(z, hprev - n, n);    // (1-z)*n + z*h
            unsigned long long w = ((unsigned long long)(unsigned)(t + 2) << 32)
                                 | (unsigned long long)__float_as_uint(hnew);
            st_rel_u64(&g_ht[(t + 1) & 1][jj], w);
        }
        // no trailing barrier: hs is double-buffered; overwrite of hs[b] occurs at
        // step t+2 whose poll is gated on tags that prove every warp published t+1,
        // and each publish data-depends on that warp's completed reads of hs[b].
    }
}

// ---------------- final projection: logits = h @ W_out + b_out -----------------
// final h (t=2048, tag 2049) lives in g_ht[0] low words
__global__ void logits_kernel(const float* __restrict__ W_out,
                              const float* __restrict__ b_out)
{
    __shared__ float hsm[HDIM];
    for (int i = threadIdx.x; i < HDIM; i += 256)
        hsm[i] = __uint_as_float((unsigned)g_ht[0][i]);
    __syncthreads();
    int v = blockIdx.x*256 + threadIdx.x;
    if (v >= VOCAB) return;
    float acc = b_out[v];
    #pragma unroll 4
    for (int d = 0; d < HDIM; d++) acc += hsm[d]*W_out[(long long)d*VOCAB + v];
    g_logits[v] = acc;
}

__global__ void lse_kernel()
{
    __shared__ float red[32];
    int tid = threadIdx.x;                         // 1024
    float m = -1e30f;
    for (int i = tid; i < VOCAB; i += 1024) m = fmaxf(m, g_logits[i]);
    #pragma unroll
    for (int o = 16; o > 0; o >>= 1) m = fmaxf(m, __shfl_xor_sync(~0u, m, o));
    if ((tid & 31) == 0) red[tid >> 5] = m;
    __syncthreads();
    if (tid == 0) {
        float x = red[0];
        #pragma unroll
        for (int i = 1; i < 32; i++) x = fmaxf(x, red[i]);
        red[0] = x;
    }
    __syncthreads();
    m = red[0];
    __syncthreads();
    float s = 0.0f;
    for (int i = tid; i < VOCAB; i += 1024) s += expf(g_logits[i] - m);
    #pragma unroll
    for (int o = 16; o > 0; o >>= 1) s += __shfl_xor_sync(~0u, s, o);
    if ((tid & 31) == 0) red[tid >> 5] = s;
    __syncthreads();
    if (tid == 0) {
        float x = 0.0f;
        #pragma unroll
        for (int i = 0; i < 32; i++) x += red[i];
        g_lse = m + logf(x);
    }
}

__global__ void out_kernel(float* __restrict__ out)
{
    int i = blockIdx.x*256 + threadIdx.x;
    if (i < VOCAB)            out[i] = g_logits[i] - g_lse;
    else if (i < VOCAB+HDIM)  out[i] = __uint_as_float((unsigned)g_ht[0][i - VOCAB]);
}

// ================================ host side =====================================
extern "C" void kernel_launch(void* const* d_in, const int* in_sizes, int n_in,
                              void* d_out, int out_size)
{
    const int*   tok     = (const int*)  d_in[0];
    const float* dec_hid = (const float*)d_in[1];
    const float* emb     = (const float*)d_in[2];
    const float* Wq      = (const float*)d_in[3];
    const float* bq      = (const float*)d_in[4];
    const float* Wk      = (const float*)d_in[5];
    const float* bk      = (const float*)d_in[6];
    const float* Wv      = (const float*)d_in[7];
    const float* bv      = (const float*)d_in[8];
    const float* Wo      = (const float*)d_in[9];
    const float* bo      = (const float*)d_in[10];
    const float* gamma   = (const float*)d_in[11];
    const float* beta    = (const float*)d_in[12];
    const float* W_ih    = (const float*)d_in[13];
    const float* W_hh    = (const float*)d_in[14];
    const float* b_ih    = (const float*)d_in[15];
    const float* b_hh    = (const float*)d_in[16];
    const float* W_out   = (const float*)d_in[17];
    const float* b_out   = (const float*)d_in[18];
    float* out = (float*)d_out;

    float *px, *pq, *pk, *pV, *psc, *pcat, *pmha, *pxln, *pgi;
    cudaGetSymbolAddress((void**)&px,   g_x);
    cudaGetSymbolAddress((void**)&pq,   g_q);
    cudaGetSymbolAddress((void**)&pk,   g_k);
    cudaGetSymbolAddress((void**)&pV,   g_v);
    cudaGetSymbolAddress((void**)&psc,  g_sc);
    cudaGetSymbolAddress((void**)&pcat, g_cat);
    cudaGetSymbolAddress((void**)&pmha, g_mha);
    cudaGetSymbolAddress((void**)&pxln, g_xln);
    cudaGetSymbolAddress((void**)&pgi,  g_gi);

    // 1) embedding gather
    embed_kernel<<<SEQ, 128>>>(tok, emb);

    // 2) Q/K/V projections: (2048x512)@(512x512) per head, batched over heads
    gemm128<false><<<dim3(8,16,NH), 256>>>(px, Wq, bq, pq, SEQ, HDIM, HDIM,
        HDIM, HDIM, HDIM, 0LL, (long long)HDIM*HDIM, (long long)SEQ*HDIM, HDIM, 1.0f);
    gemm128<false><<<dim3(8,16,NH), 256>>>(px, Wk, bk, pk, SEQ, HDIM, HDIM,
        HDIM, HDIM, HDIM, 0LL, (long long)HDIM*HDIM, (long long)SEQ*HDIM, HDIM, 1.0f);
    gemm128<false><<<dim3(8,16,NH), 256>>>(px, Wv, bv, pV, SEQ, HDIM, HDIM,
        HDIM, HDIM, HDIM, 0LL, (long long)HDIM*HDIM, (long long)SEQ*HDIM, HDIM, 1.0f);

    // 3) scores = Q @ K^T / sqrt(H)
    gemm128<true><<<dim3(32,16,NH), 256>>>(pq, pk, (const float*)0, psc,
        SEQ, SEQ, HDIM, HDIM, HDIM, SEQ,
        (long long)SEQ*HDIM, (long long)SEQ*HDIM, (long long)SEQ*SEQ, 0LL,
        0.04419417382415922f);

    // 4) softmax over last dim
    softmax2048<<<NH*SEQ, 256>>>(psc);

    // 5) heads = P @ V, written directly into concat layout (col offset h*512)
    gemm128<false><<<dim3(8,16,NH), 256>>>(psc, pV, (const float*)0, pcat,
        SEQ, HDIM, SEQ, SEQ, HDIM, NH*HDIM,
        (long long)SEQ*SEQ, (long long)SEQ*HDIM, (long long)HDIM, 0LL, 1.0f);

    // 6) mha = cat @ Wo + bo
    gemm128<false><<<dim3(8,16,1), 256>>>(pcat, Wo, bo, pmha,
        SEQ, HDIM, NH*HDIM, NH*HDIM, HDIM, HDIM, 0LL, 0LL, 0LL, 0LL, 1.0f);

    // 7) residual + layernorm
    resid_ln<<<SEQ, 256>>>(gamma, beta);

    // 8) gi = xln @ W_ih^T + b_ih (all timesteps, parallel)
    gemm128<true><<<dim3(24,16,1), 256>>>(pxln, W_ih, b_ih, pgi,
        SEQ, G3, HDIM, HDIM, HDIM, G3, 0LL, 0LL, 0LL, 0LL, 1.0f);

    // 9) sequential GRU (persistent, register-resident W_hh, tag-word dataflow)
    gru_init<<<1, 512>>>(dec_hid);
    gru_kernel<<<GRU_NCTA, 256>>>(W_hh, b_hh);

    // 10) logits + log_softmax + outputs
    logits_kernel<<<(VOCAB+255)/256, 256>>>(W_out, b_out);
    lse_kernel<<<1, 1024>>>();
    out_kernel<<<(VOCAB+HDIM+255)/256, 256>>>(out);
}

// round 12
// speedup vs baseline: 1.4349x; 1.2905x over previous
#include <cuda_runtime.h>
#include <cuda_bf16.h>
#include <math.h>
#include <stdint.h>

#define SEQ   2048
#define HDIM  512
#define NH    6
#define VOCAB 32000
#define G3    1536          // 3*HDIM
#define GRU_NCTA 64         // 64 CTAs x 256 threads (best measured shape)

// ---------------- scratch (device globals; no allocations allowed) -------------
__device__ float g_x   [SEQ*HDIM];                 // embeddings
__device__ float g_q   [NH*SEQ*HDIM];
__device__ float g_k   [NH*SEQ*HDIM];
__device__ float g_v   [NH*SEQ*HDIM];
__device__ float g_sc  [(size_t)NH*SEQ*SEQ];       // attention scores / probs
__device__ float g_cat [SEQ*NH*HDIM];              // concatenated heads (s, h*512+e)
__device__ float g_mha [SEQ*HDIM];
__device__ float g_xln [SEQ*HDIM];                 // post-LN sequence (GRU input)
__device__ float g_gi  [SEQ*G3];                   // x @ W_ih^T + b_ih, all timesteps
__device__ unsigned long long g_ht[2][HDIM];       // tagged hidden: (tag<<32)|f32bits
__device__ float g_logits[VOCAB];
__device__ float g_lse;
// bf16 operands for tensor-core attention
__device__ __nv_bfloat16 g_qb [NH*SEQ*HDIM];       // Q bf16 [h][s][e]
__device__ __nv_bfloat16 g_kb [NH*SEQ*HDIM];       // K bf16 [h][s][e]
__device__ __nv_bfloat16 g_vtb[NH*HDIM*SEQ];       // V^T bf16 [h][e][t]
__device__ __nv_bfloat16 g_pb [(size_t)NH*SEQ*SEQ];// P bf16 [h][s][t]

// STRONG (morally strong -> single-copy atomic per PTX model) 64-bit ops.
__device__ __forceinline__ unsigned long long ld_acq_u64(const unsigned long long* p){
    unsigned long long v;
    asm volatile("ld.acquire.gpu.global.u64 %0, [%1];" : "=l"(v) : "l"(p) : "memory");
    return v;
}
__device__ __forceinline__ void st_rel_u64(unsigned long long* p, unsigned long long v){
    asm volatile("st.release.gpu.global.u64 [%0], %1;" :: "l"(p), "l"(v) : "memory");
}
__device__ __forceinline__ float tanh_fast(float x){
    float y; asm("tanh.approx.f32 %0, %1;" : "=f"(y) : "f"(x)); return y;
}

// ---------------- mma.sync m16n8k16 bf16 (baseline PTX; HMMA on sm_103) --------
__device__ __forceinline__ void mma16816(float* c, const uint32_t* a, const uint32_t* b){
    asm volatile(
      "mma.sync.aligned.m16n8k16.row.col.f32.bf16.bf16.f32 "
      "{%0,%1,%2,%3}, {%4,%5,%6,%7}, {%8,%9}, {%0,%1,%2,%3};"
      : "+f"(c[0]), "+f"(c[1]), "+f"(c[2]), "+f"(c[3])
      : "r"(a[0]), "r"(a[1]), "r"(a[2]), "r"(a[3]), "r"(b[0]), "r"(b[1]));
}

// ---------------- embedding gather ---------------------------------------------
__global__ void embed_kernel(const int* __restrict__ tok,
                             const float* __restrict__ emb)
{
    int s = blockIdx.x;
    long long t = tok[s];
    const float4* src = (const float4*)(emb + t*HDIM);
    float4* dst = (float4*)(g_x + (long long)s*HDIM);
    int i = threadIdx.x;               // 128 threads, 128 float4 = 512 floats
    dst[i] = src[i];
}

// ---------------- fp32 tiled GEMM (R6, at the fp32 SIMT wall) ------------------
template<bool TRANS_B>
__global__ void __launch_bounds__(256, 2)
gemm128(const float* __restrict__ A, const float* __restrict__ B,
        const float* __restrict__ bias, float* __restrict__ C,
        int M, int N, int K, int lda, int ldb, int ldc,
        long long sA, long long sB, long long sC, long long sBias,
        float alpha)
{
    __shared__ float As[2][16][132];
    __shared__ float Bs[2][16][68];
    A += (long long)blockIdx.z * sA;
    B += (long long)blockIdx.z * sB;
    C += (long long)blockIdx.z * sC;
    const float* bi = bias ? (bias + (long long)blockIdx.z * sBias) : (const float*)0;

    const int bm = blockIdx.y * 128;
    const int bn = blockIdx.x * 64;
    const int tid = threadIdx.x;
    const int tx = tid & 15, ty = tid >> 4;

    float acc[8][4];
    #pragma unroll
    for (int i = 0; i < 8; i++)
        #pragma unroll
        for (int j = 0; j < 4; j++) acc[i][j] = 0.0f;

    float ra[8], rb[4];

    #pragma unroll
    for (int i = 0; i < 8; i++) {
        int idx = tid + i*256;
        int m = idx >> 4, k = idx & 15;
        ra[i] = A[(long long)(bm+m)*lda + k];
    }
    #pragma unroll
    for (int i = 0; i < 4; i++) {
        int idx = tid + i*256;
        if (TRANS_B) { int n = idx >> 4, k = idx & 15; rb[i] = B[(long long)(bn+n)*ldb + k]; }
        else         { int k = idx >> 6, n = idx & 63; rb[i] = B[(long long)k*ldb + (bn+n)]; }
    }
    #pragma unroll
    for (int i = 0; i < 8; i++) {
        int idx = tid + i*256;
        int m = idx >> 4, k = idx & 15;
        As[0][k][m] = ra[i];
    }
    #pragma unroll
    for (int i = 0; i < 4; i++) {
        int idx = tid + i*256;
        if (TRANS_B) { int n = idx >> 4, k = idx & 15; Bs[0][k][n] = rb[i]; }
        else         { int k = idx >> 6, n = idx & 63; Bs[0][k][n] = rb[i]; }
    }
    __syncthreads();

    int cur = 0;
    for (int k0 = 0; k0 < K; k0 += 16) {
        const bool has_next = (k0 + 16 < K);
        if (has_next) {
            const int kn = k0 + 16;
            #pragma unroll
            for (int i = 0; i < 8; i++) {
                int idx = tid + i*256;
                int m = idx >> 4, k = idx & 15;
                ra[i] = A[(long long)(bm+m)*lda + (kn+k)];
            }
            #pragma unroll
            for (int i = 0; i < 4; i++) {
                int idx = tid + i*256;
                if (TRANS_B) { int n = idx >> 4, k = idx & 15; rb[i] = B[(long long)(bn+n)*ldb + (kn+k)]; }
                else         { int k = idx >> 6, n = idx & 63; rb[i] = B[(long long)(kn+k)*ldb + (bn+n)]; }
            }
        }
        #pragma unroll
        for (int kk = 0; kk < 16; kk++) {
            float4 a0 = *(const float4*)&As[cur][kk][ty*8];
            float4 a1 = *(const float4*)&As[cur][kk][ty*8+4];
            float4 b0 = *(const float4*)&Bs[cur][kk][tx*4];
            float af[8] = {a0.x,a0.y,a0.z,a0.w,a1.x,a1.y,a1.z,a1.w};
            float bf[4] = {b0.x,b0.y,b0.z,b0.w};
            #pragma unroll
            for (int i = 0; i < 8; i++)
                #pragma unroll
                for (int j = 0; j < 4; j++)
                    acc[i][j] += af[i]*bf[j];
        }
        if (has_next) {
            const int nxt = cur ^ 1;
            #pragma unroll
            for (int i = 0; i < 8; i++) {
                int idx = tid + i*256;
                int m = idx >> 4, k = idx & 15;
                As[nxt][k][m] = ra[i];
            }
            #pragma unroll
            for (int i = 0; i < 4; i++) {
                int idx = tid + i*256;
                if (TRANS_B) { int n = idx >> 4, k = idx & 15; Bs[nxt][k][n] = rb[i]; }
                else         { int k = idx >> 6, n = idx & 63; Bs[nxt][k][n] = rb[i]; }
            }
            __syncthreads();
            cur = nxt;
        }
    }
    #pragma unroll
    for (int i = 0; i < 8; i++) {
        int row = bm + ty*8 + i;
        float* cp = C + (long long)row*ldc + bn + tx*4;
        #pragma unroll
        for (int j = 0; j < 4; j++) {
            float vv = alpha*acc[i][j];
            if (bi) vv += bi[bn + tx*4 + j];
            cp[j] = vv;
        }
    }
}

// ---------------- fp32 -> bf16 convert (grid-stride) ---------------------------
__global__ void cvt_bf16(const float* __restrict__ src, __nv_bfloat16* __restrict__ dst,
                         long long n)
{
    long long i = (long long)blockIdx.x*blockDim.x + threadIdx.x;
    long long stride = (long long)gridDim.x*blockDim.x;
    for (; i < n; i += stride) dst[i] = __float2bfloat16(src[i]);
}

// ---------------- V transpose + convert: vtb[h][e][t] = bf16(V[h][t][e]) -------
__global__ void transpose_v_kernel()
{
    __shared__ float tile[32][33];
    int h = blockIdx.z;
    int t0 = blockIdx.x*32, e0 = blockIdx.y*32;
    int tx = threadIdx.x, ty = threadIdx.y;      // 32 x 8
    const float* V = g_v + (long long)h*SEQ*HDIM;
    #pragma unroll
    for (int i = 0; i < 4; i++)
        tile[ty + i*8][tx] = V[(long long)(t0 + ty + i*8)*HDIM + e0 + tx];
    __syncthreads();
    __nv_bfloat16* Vt = g_vtb + (long long)h*HDIM*SEQ;
    #pragma unroll
    for (int i = 0; i < 4; i++)
        Vt[(long long)(e0 + ty + i*8)*SEQ + t0 + tx] = __float2bfloat16(tile[tx][ty + i*8]);
}

// ---------------- HMMA bf16 GEMM: C = alpha * (A @ B^T) ------------------------
// A: [M, KTOT] bf16 K-major, B: [N, KTOT] bf16 K-major, C fp32.
// CTA: 256 threads (8 warps in a 4x2 grid), tile 128x64; warp tile 32x32 =
// 2x4 m16n8k16 mma tiles. K staged through smem in chunks of 64.
// All fragment loads are plain aligned b32 LDS (K-major layouts make every
// fragment register two k-adjacent bf16).
__global__ void __launch_bounds__(256)
attn_mma(const __nv_bfloat16* __restrict__ A, const __nv_bfloat16* __restrict__ B,
         float* __restrict__ C, int KTOT, int ldc,
         long long sA, long long sB, long long sC, float alpha)
{
    __shared__ __align__(16) __nv_bfloat16 As[128][72];
    __shared__ __align__(16) __nv_bfloat16 Bs[64][72];

    const int tid = threadIdx.x;
    const int wid = tid >> 5, lane = tid & 31;
    const int wm = wid >> 1, wn = wid & 1;       // warp grid 4 x 2
    const int g = lane >> 2, t = lane & 3;       // mma fragment coords

    const int h = blockIdx.z;
    const __nv_bfloat16* Ag = A + (long long)h*sA + (long long)(blockIdx.y*128)*KTOT;
    const __nv_bfloat16* Bg = B + (long long)h*sB + (long long)(blockIdx.x*64)*KTOT;

    float acc[2][4][4];
    #pragma unroll
    for (int mi = 0; mi < 2; mi++)
        #pragma unroll
        for (int ni = 0; ni < 4; ni++)
            #pragma unroll
            for (int r = 0; r < 4; r++) acc[mi][ni][r] = 0.0f;

    for (int k0 = 0; k0 < KTOT; k0 += 64) {
        __syncthreads();                          // previous-iter reads done
        // A chunk: 128 rows x 64 bf16 = 1024 uint4; 4 per thread
        #pragma unroll
        for (int i = 0; i < 4; i++) {
            int idx = tid + i*256;
            int row = idx >> 3, c8 = idx & 7;
            uint4 v = *(const uint4*)(Ag + (long long)row*KTOT + k0 + c8*8);
            *(uint4*)&As[row][c8*8] = v;
        }
        // B chunk: 64 rows x 64 bf16 = 512 uint4; 2 per thread
        #pragma unroll
        for (int i = 0; i < 2; i++) {
            int idx = tid + i*256;
            int row = idx >> 3, c8 = idx & 7;
            uint4 v = *(const uint4*)(Bg + (long long)row*KTOT + k0 + c8*8);
            *(uint4*)&Bs[row][c8*8] = v;
        }
        __syncthreads();

        #pragma unroll
        for (int ks = 0; ks < 4; ks++) {
            const int kk = ks*16;
            uint32_t a[2][4], b[4][2];
            #pragma unroll
            for (int mi = 0; mi < 2; mi++) {
                int m0 = wm*32 + mi*16;
                a[mi][0] = *(const uint32_t*)&As[m0 + g    ][kk + t*2    ];
                a[mi][1] = *(const uint32_t*)&As[m0 + g + 8][kk + t*2    ];
                a[mi][2] = *(const uint32_t*)&As[m0 + g    ][kk + t*2 + 8];
                a[mi][3] = *(const uint32_t*)&As[m0 + g + 8][kk + t*2 + 8];
            }
            #pragma unroll
            for (int ni = 0; ni < 4; ni++) {
                int n0 = wn*32 + ni*8;
                b[ni][0] = *(const uint32_t*)&Bs[n0 + g][kk + t*2    ];
                b[ni][1] = *(const uint32_t*)&Bs[n0 + g][kk + t*2 + 8];
            }
            #pragma unroll
            for (int mi = 0; mi < 2; mi++)
                #pragma unroll
                for (int ni = 0; ni < 4; ni++)
                    mma16816(acc[mi][ni], a[mi], b[ni]);
        }
    }

    // epilogue: c0,c1 -> (row g, cols 2t,2t+1); c2,c3 -> row g+8
    const int base_m = blockIdx.y*128 + wm*32;
    const int base_n = blockIdx.x*64  + wn*32;
    float* Cg = C + (long long)h*sC;
    #pragma unroll
    for (int mi = 0; mi < 2; mi++) {
        #pragma unroll
        for (int ni = 0; ni < 4; ni++) {
            int r0 = base_m + mi*16 + g;
            int c0 = base_n + ni*8 + t*2;
            float2 lo = make_float2(alpha*acc[mi][ni][0], alpha*acc[mi][ni][1]);
            float2 hi = make_float2(alpha*acc[mi][ni][2], alpha*acc[mi][ni][3]);
            *(float2*)(Cg + (long long)r0*ldc + c0)       = lo;
            *(float2*)(Cg + (long long)(r0 + 8)*ldc + c0) = hi;
        }
    }
}

// ---------------- row softmax over length-2048 rows ----------------------------
__global__ void softmax2048(float* __restrict__ S)
{
    __shared__ float red[32];
    float* row = S + (long long)blockIdx.x * 2048;
    int tid = threadIdx.x;                         // 256
    float v[8];
    float m = -1e30f;
    #pragma unroll
    for (int i = 0; i < 8; i++) { v[i] = row[tid + i*256]; m = fmaxf(m, v[i]); }
    #pragma unroll
    for (int o = 16; o > 0; o >>= 1) m = fmaxf(m, __shfl_xor_sync(~0u, m, o));
    if ((tid & 31) == 0) red[tid >> 5] = m;
    __syncthreads();
    if (tid == 0) {
        float x = red[0];
        #pragma unroll
        for (int i = 1; i < 8; i++) x = fmaxf(x, red[i]);
        red[0] = x;
    }
    __syncthreads();
    m = red[0];
    __syncthreads();
    float s = 0.0f;
    #pragma unroll
    for (int i = 0; i < 8; i++) { v[i] = __expf(v[i] - m); s += v[i]; }
    #pragma unroll
    for (int o = 16; o > 0; o >>= 1) s += __shfl_xor_sync(~0u, s, o);
    if ((tid & 31) == 0) red[tid >> 5] = s;
    __syncthreads();
    if (tid == 0) {
        float x = 0.0f;
        #pragma unroll
        for (int i = 0; i < 8; i++) x += red[i];
        red[0] = x;
    }
    __syncthreads();
    float inv = 1.0f / red[0];
    #pragma unroll
    for (int i = 0; i < 8; i++) row[tid + i*256] = v[i]*inv;
}

// ---------------- residual + LayerNorm -----------------------------------------
__global__ void resid_ln(const float* __restrict__ gamma, const float* __restrict__ beta)
{
    __shared__ float r1[8], r2[8];
    int s = blockIdx.x, tid = threadIdx.x;         // 256 threads
    const float* xr = g_x   + (long long)s*HDIM;
    const float* mr = g_mha + (long long)s*HDIM;
    float y0 = xr[tid]       + mr[tid];
    float y1 = xr[tid + 256] + mr[tid + 256];
    float sum = y0 + y1, sq = y0*y0 + y1*y1;
    #pragma unroll
    for (int o = 16; o > 0; o >>= 1) {
        sum += __shfl_xor_sync(~0u, sum, o);
        sq  += __shfl_xor_sync(~0u, sq,  o);
    }
    if ((tid & 31) == 0) { r1[tid >> 5] = sum; r2[tid >> 5] = sq; }
    __syncthreads();
    if (tid == 0) {
        float a = 0.0f, b = 0.0f;
        #pragma unroll
        for (int i = 0; i < 8; i++) { a += r1[i]; b += r2[i]; }
        r1[0] = a; r2[0] = b;
    }
    __syncthreads();
    float mu  = r1[0]*(1.0f/512.0f);
    float var = r2[0]*(1.0f/512.0f) - mu*mu;
    float rstd = rsqrtf(var + 1e-5f);
    g_xln[(long long)s*HDIM + tid]       = (y0 - mu)*rstd*gamma[tid]       + beta[tid];
    g_xln[(long long)s*HDIM + 256 + tid] = (y1 - mu)*rstd*gamma[tid + 256] + beta[tid + 256];
}

// ---------------- GRU init: seed h with tag=1, clear stale tags (graph replay!) -
__global__ void gru_init(const float* __restrict__ dec_hid)
{
    int i = threadIdx.x;                           // 512
    g_ht[0][i] = (1ULL << 32) | (unsigned long long)__float_as_uint(dec_hid[i]);
    g_ht[1][i] = 0ULL;                             // stale-tag clear
}

// ---------------- persistent sequential GRU (R6 version: best measured) --------
__global__ void gru_kernel(const float* __restrict__ W_hh,
                           const float* __restrict__ b_hh)
{
    __shared__ float hs[2][HDIM];
    const int tid = threadIdx.x;
    const int warp = tid >> 5, lane = tid & 31;
    const int jj = blockIdx.x * 8 + warp;          // 0..511

    float wr0[16], wr1[16], wr2[16];
    const float* w0 = W_hh + (long long)(jj        )*HDIM + lane;
    const float* w1 = W_hh + (long long)(jj +  512 )*HDIM + lane;
    const float* w2 = W_hh + (long long)(jj + 1024 )*HDIM + lane;
    #pragma unroll
    for (int i = 0; i < 16; i++) { wr0[i] = w0[32*i]; wr1[i] = w1[32*i]; wr2[i] = w2[32*i]; }
    const float bh0 = b_hh[jj], bh1 = b_hh[jj + 512], bh2 = b_hh[jj + 1024];

    for (int t = 0; t < SEQ; t++) {
        float gr = __ldcg(&g_gi[(long long)t*G3 + jj]);
        float gz = __ldcg(&g_gi[(long long)t*G3 + jj + 512]);
        float gn = __ldcg(&g_gi[(long long)t*G3 + jj + 1024]);

        const unsigned long long* hb = g_ht[t & 1];
        const unsigned expect = (unsigned)(t + 1);
        unsigned long long v0 = ld_acq_u64(&hb[tid]);
        unsigned long long v1 = ld_acq_u64(&hb[tid + 256]);
        while ((unsigned)(v0 >> 32) != expect) v0 = ld_acq_u64(&hb[tid]);
        while ((unsigned)(v1 >> 32) != expect) v1 = ld_acq_u64(&hb[tid + 256]);

        float* hcur = hs[t & 1];
        hcur[tid]       = __uint_as_float((unsigned)v0);
        hcur[tid + 256] = __uint_as_float((unsigned)v1);
        __syncthreads();

        float hprev = hcur[jj];
        float a0 = 0.0f, a1 = 0.0f, a2 = 0.0f;
        #pragma unroll
        for (int i = 0; i < 16; i++) {
            float h = hcur[lane + 32*i];
            a0 += h*wr0[i];
            a1 += h*wr1[i];
            a2 += h*wr2[i];
        }
        #pragma unroll
        for (int o = 16; o > 0; o >>= 1) {
            a0 += __shfl_xor_sync(~0u, a0, o);
            a1 += __shfl_xor_sync(~0u, a1, o);
            a2 += __shfl_xor_sync(~0u, a2, o);
        }

        if (lane == 0) {
            float r = 0.5f + 0.5f*tanh_fast(0.5f*(gr + a0 + bh0));
            float z = 0.5f + 0.5f*tanh_fast(0.5f*(gz + a1 + bh1));
            float n = tanh_fast(gn + r*(a2 + bh2));
            float hnew = fmaf(z, hprev - n, n);    // (1-z)*n + z*h
            unsigned long long w = ((unsigned long long)(unsigned)(t + 2) << 32)
                                 | (unsigned long long)__float_as_uint(hnew);
            st_rel_u64(&g_ht[(t + 1) & 1][jj], w);
        }
        // no trailing barrier: hs double-buffered; overwrite gated by tag chain.
    }
}

// ---------------- final projection: logits = h @ W_out + b_out -----------------
__global__ void logits_kernel(const float* __restrict__ W_out,
                              const float* __restrict__ b_out)
{
    __shared__ float hsm[HDIM];
    for (int i = threadIdx.x; i < HDIM; i += 256)
        hsm[i] = __uint_as_float((unsigned)g_ht[0][i]);
    __syncthreads();
    int v = blockIdx.x*256 + threadIdx.x;
    if (v >= VOCAB) return;
    float acc = b_out[v];
    #pragma unroll 4
    for (int d = 0; d < HDIM; d++) acc += hsm[d]*W_out[(long long)d*VOCAB + v];
    g_logits[v] = acc;
}

__global__ void lse_kernel()
{
    __shared__ float red[32];
    int tid = threadIdx.x;                         // 1024
    float m = -1e30f;
    for (int i = tid; i < VOCAB; i += 1024) m = fmaxf(m, g_logits[i]);
    #pragma unroll
    for (int o = 16; o > 0; o >>= 1) m = fmaxf(m, __shfl_xor_sync(~0u, m, o));
    if ((tid & 31) == 0) red[tid >> 5] = m;
    __syncthreads();
    if (tid == 0) {
        float x = red[0];
        #pragma unroll
        for (int i = 1; i < 32; i++) x = fmaxf(x, red[i]);
        red[0] = x;
    }
    __syncthreads();
    m = red[0];
    __syncthreads();
    float s = 0.0f;
    for (int i = tid; i < VOCAB; i += 1024) s += expf(g_logits[i] - m);
    #pragma unroll
    for (int o = 16; o > 0; o >>= 1) s += __shfl_xor_sync(~0u, s, o);
    if ((tid & 31) == 0) red[tid >> 5] = s;
    __syncthreads();
    if (tid == 0) {
        float x = 0.0f;
        #pragma unroll
        for (int i = 0; i < 32; i++) x += red[i];
        g_lse = m + logf(x);
    }
}

__global__ void out_kernel(float* __restrict__ out)
{
    int i = blockIdx.x*256 + threadIdx.x;
    if (i < VOCAB)            out[i] = g_logits[i] - g_lse;
    else if (i < VOCAB+HDIM)  out[i] = __uint_as_float((unsigned)g_ht[0][i - VOCAB]);
}

// ================================ host side =====================================
extern "C" void kernel_launch(void* const* d_in, const int* in_sizes, int n_in,
                              void* d_out, int out_size)
{
    const int*   tok     = (const int*)  d_in[0];
    const float* dec_hid = (const float*)d_in[1];
    const float* emb     = (const float*)d_in[2];
    const float* Wq      = (const float*)d_in[3];
    const float* bq      = (const float*)d_in[4];
    const float* Wk      = (const float*)d_in[5];
    const float* bk      = (const float*)d_in[6];
    const float* Wv      = (const float*)d_in[7];
    const float* bv      = (const float*)d_in[8];
    const float* Wo      = (const float*)d_in[9];
    const float* bo      = (const float*)d_in[10];
    const float* gamma   = (const float*)d_in[11];
    const float* beta    = (const float*)d_in[12];
    const float* W_ih    = (const float*)d_in[13];
    const float* W_hh    = (const float*)d_in[14];
    const float* b_ih    = (const float*)d_in[15];
    const float* b_hh    = (const float*)d_in[16];
    const float* W_out   = (const float*)d_in[17];
    const float* b_out   = (const float*)d_in[18];
    float* out = (float*)d_out;

    float *px, *pq, *pk, *pV, *psc, *pcat, *pmha, *pxln, *pgi;
    cudaGetSymbolAddress((void**)&px,   g_x);
    cudaGetSymbolAddress((void**)&pq,   g_q);
    cudaGetSymbolAddress((void**)&pk,   g_k);
    cudaGetSymbolAddress((void**)&pV,   g_v);
    cudaGetSymbolAddress((void**)&psc,  g_sc);
    cudaGetSymbolAddress((void**)&pcat, g_cat);
    cudaGetSymbolAddress((void**)&pmha, g_mha);
    cudaGetSymbolAddress((void**)&pxln, g_xln);
    cudaGetSymbolAddress((void**)&pgi,  g_gi);
    __nv_bfloat16 *pqb, *pkb, *pvtb, *ppb;
    cudaGetSymbolAddress((void**)&pqb,  g_qb);
    cudaGetSymbolAddress((void**)&pkb,  g_kb);
    cudaGetSymbolAddress((void**)&pvtb, g_vtb);
    cudaGetSymbolAddress((void**)&ppb,  g_pb);

    // 1) embedding gather
    embed_kernel<<<SEQ, 128>>>(tok, emb);

    // 2) Q/K/V projections (fp32 SIMT wall)
    gemm128<false><<<dim3(8,16,NH), 256>>>(px, Wq, bq, pq, SEQ, HDIM, HDIM,
        HDIM, HDIM, HDIM, 0LL, (long long)HDIM*HDIM, (long long)SEQ*HDIM, HDIM, 1.0f);
    gemm128<false><<<dim3(8,16,NH), 256>>>(px, Wk, bk, pk, SEQ, HDIM, HDIM,
        HDIM, HDIM, HDIM, 0LL, (long long)HDIM*HDIM, (long long)SEQ*HDIM, HDIM, 1.0f);
    gemm128<false><<<dim3(8,16,NH), 256>>>(px, Wv, bv, pV, SEQ, HDIM, HDIM,
        HDIM, HDIM, HDIM, 0LL, (long long)HDIM*HDIM, (long long)SEQ*HDIM, HDIM, 1.0f);

    // 3) bf16 operand prep
    cvt_bf16<<<2048, 256>>>(pq, pqb, (long long)NH*SEQ*HDIM);
    cvt_bf16<<<2048, 256>>>(pk, pkb, (long long)NH*SEQ*HDIM);
    transpose_v_kernel<<<dim3(SEQ/32, HDIM/32, NH), dim3(32,8)>>>();

    // 4) scores = Q @ K^T / sqrt(H)  — HMMA bf16 (KTOT=512)
    attn_mma<<<dim3(SEQ/64, SEQ/128, NH), 256>>>(
        pqb, pkb, psc, HDIM, SEQ,
        (long long)SEQ*HDIM, (long long)SEQ*HDIM, (long long)SEQ*SEQ,
        0.04419417382415922f);

    // 5) softmax over last dim
    softmax2048<<<NH*SEQ, 256>>>(psc);

    // 6) P -> bf16
    cvt_bf16<<<8192, 256>>>(psc, ppb, (long long)NH*SEQ*SEQ);

    // 7) heads = P @ V  (B = V^T) — HMMA bf16 (KTOT=2048), concat layout
    attn_mma<<<dim3(HDIM/64, SEQ/128, NH), 256>>>(
        ppb, pvtb, pcat, SEQ, NH*HDIM,
        (long long)SEQ*SEQ, (long long)HDIM*SEQ, (long long)HDIM, 1.0f);

    // 8) mha = cat @ Wo + bo
    gemm128<false><<<dim3(8,16,1), 256>>>(pcat, Wo, bo, pmha,
        SEQ, HDIM, NH*HDIM, NH*HDIM, HDIM, HDIM, 0LL, 0LL, 0LL, 0LL, 1.0f);

    // 9) residual + layernorm
    resid_ln<<<SEQ, 256>>>(gamma, beta);

    // 10) gi = xln @ W_ih^T + b_ih (fp32 for GRU precision)
    gemm128<true><<<dim3(24,16,1), 256>>>(pxln, W_ih, b_ih, pgi,
        SEQ, G3, HDIM, HDIM, HDIM, G3, 0LL, 0LL, 0LL, 0LL, 1.0f);

    // 11) sequential GRU (R6 best configuration)
    gru_init<<<1, 512>>>(dec_hid);
    gru_kernel<<<GRU_NCTA, 256>>>(W_hh, b_hh);

    // 12) logits + log_softmax + outputs
    logits_kernel<<<(VOCAB+255)/256, 256>>>(W_out, b_out);
    lse_kernel<<<1, 1024>>>();
    out_kernel<<<(VOCAB+HDIM+255)/256, 256>>>(out);
}

// round 14
// speedup vs baseline: 1.6453x; 1.1467x over previous
#include <cuda_runtime.h>
#include <cuda_bf16.h>
#include <math.h>
#include <stdint.h>

#define SEQ   2048
#define HDIM  512
#define NH    6
#define VOCAB 32000
#define G3    1536          // 3*HDIM
#define GRU_NCTA 64         // 64 CTAs x 256 threads (best measured shape)

// ---------------- scratch (device globals; no allocations allowed) -------------
__device__ float g_x   [SEQ*HDIM];                 // embeddings (fp32, residual path)
__device__ float g_sc  [(size_t)NH*SEQ*SEQ];       // attention scores / probs
__device__ float g_mha [SEQ*HDIM];
__device__ float g_xln [SEQ*HDIM];                 // post-LN sequence (GRU input)
__device__ float g_gi  [SEQ*G3];                   // xln @ W_ih^T + b_ih
__device__ unsigned long long g_ht[2][HDIM];       // tagged hidden: (tag<<32)|f32bits
__device__ float g_logits[VOCAB];
__device__ float g_lse;
// bf16 operands
__device__ __nv_bfloat16 g_xb  [SEQ*HDIM];         // x bf16
__device__ __nv_bfloat16 g_wqt [NH*HDIM*HDIM];     // Wq^T per head [h][e][d]
__device__ __nv_bfloat16 g_wkt [NH*HDIM*HDIM];
__device__ __nv_bfloat16 g_wvt [NH*HDIM*HDIM];
__device__ __nv_bfloat16 g_wot [HDIM*NH*HDIM];     // Wo^T [n=512][k=3072]
__device__ __nv_bfloat16 g_qb  [NH*SEQ*HDIM];      // Q bf16 [h][s][e]
__device__ __nv_bfloat16 g_kb  [NH*SEQ*HDIM];      // K bf16 [h][s][e]
__device__ __nv_bfloat16 g_vtb [NH*HDIM*SEQ];      // V^T bf16 [h][e][t]
__device__ __nv_bfloat16 g_pb  [(size_t)NH*SEQ*SEQ];// P bf16 [h][s][t]
__device__ __nv_bfloat16 g_catb[SEQ*NH*HDIM];      // concat heads bf16 [s][h*512+e]

// STRONG (morally strong -> single-copy atomic per PTX model) 64-bit ops.
__device__ __forceinline__ unsigned long long ld_acq_u64(const unsigned long long* p){
    unsigned long long v;
    asm volatile("ld.acquire.gpu.global.u64 %0, [%1];" : "=l"(v) : "l"(p) : "memory");
    return v;
}
__device__ __forceinline__ void st_rel_u64(unsigned long long* p, unsigned long long v){
    asm volatile("st.release.gpu.global.u64 [%0], %1;" :: "l"(p), "l"(v) : "memory");
}
__device__ __forceinline__ float tanh_fast(float x){
    float y; asm("tanh.approx.f32 %0, %1;" : "=f"(y) : "f"(x)); return y;
}

// ---------------- mma.sync m16n8k16 bf16 (baseline PTX; HMMA on sm_103) --------
__device__ __forceinline__ void mma16816(float* c, const uint32_t* a, const uint32_t* b){
    asm volatile(
      "mma.sync.aligned.m16n8k16.row.col.f32.bf16.bf16.f32 "
      "{%0,%1,%2,%3}, {%4,%5,%6,%7}, {%8,%9}, {%0,%1,%2,%3};"
      : "+f"(c[0]), "+f"(c[1]), "+f"(c[2]), "+f"(c[3])
      : "r"(a[0]), "r"(a[1]), "r"(a[2]), "r"(a[3]), "r"(b[0]), "r"(b[1]));
}
__device__ __forceinline__ void store_pair(float* p, float a, float b){
    *(float2*)p = make_float2(a, b);
}
__device__ __forceinline__ void store_pair(__nv_bfloat16* p, float a, float b){
    *(__nv_bfloat162*)p = __floats2bfloat162_rn(a, b);
}

// ---------------- embedding gather ---------------------------------------------
__global__ void embed_kernel(const int* __restrict__ tok,
                             const float* __restrict__ emb)
{
    int s = blockIdx.x;
    long long t = tok[s];
    const float4* src = (const float4*)(emb + t*HDIM);
    float4* dst = (float4*)(g_x + (long long)s*HDIM);
    int i = threadIdx.x;               // 128 threads
    float4 v = src[i];
    dst[i] = v;
    __nv_bfloat16* db = g_xb + (long long)s*HDIM + i*4;
    db[0] = __float2bfloat16(v.x); db[1] = __float2bfloat16(v.y);
    db[2] = __float2bfloat16(v.z); db[3] = __float2bfloat16(v.w);
}

// ---------------- fp32 tiled GEMM (R6; used for gi only) -----------------------
template<bool TRANS_B>
__global__ void __launch_bounds__(256, 2)
gemm128(const float* __restrict__ A, const float* __restrict__ B,
        const float* __restrict__ bias, float* __restrict__ C,
        int M, int N, int K, int lda, int ldb, int ldc,
        long long sA, long long sB, long long sC, long long sBias,
        float alpha)
{
    __shared__ float As[2][16][132];
    __shared__ float Bs[2][16][68];
    A += (long long)blockIdx.z * sA;
    B += (long long)blockIdx.z * sB;
    C += (long long)blockIdx.z * sC;
    const float* bi = bias ? (bias + (long long)blockIdx.z * sBias) : (const float*)0;

    const int bm = blockIdx.y * 128;
    const int bn = blockIdx.x * 64;
    const int tid = threadIdx.x;
    const int tx = tid & 15, ty = tid >> 4;

    float acc[8][4];
    #pragma unroll
    for (int i = 0; i < 8; i++)
        #pragma unroll
        for (int j = 0; j < 4; j++) acc[i][j] = 0.0f;

    float ra[8], rb[4];

    #pragma unroll
    for (int i = 0; i < 8; i++) {
        int idx = tid + i*256;
        int m = idx >> 4, k = idx & 15;
        ra[i] = A[(long long)(bm+m)*lda + k];
    }
    #pragma unroll
    for (int i = 0; i < 4; i++) {
        int idx = tid + i*256;
        if (TRANS_B) { int n = idx >> 4, k = idx & 15; rb[i] = B[(long long)(bn+n)*ldb + k]; }
        else         { int k = idx >> 6, n = idx & 63; rb[i] = B[(long long)k*ldb + (bn+n)]; }
    }
    #pragma unroll
    for (int i = 0; i < 8; i++) {
        int idx = tid + i*256;
        int m = idx >> 4, k = idx & 15;
        As[0][k][m] = ra[i];
    }
    #pragma unroll
    for (int i = 0; i < 4; i++) {
        int idx = tid + i*256;
        if (TRANS_B) { int n = idx >> 4, k = idx & 15; Bs[0][k][n] = rb[i]; }
        else         { int k = idx >> 6, n = idx & 63; Bs[0][k][n] = rb[i]; }
    }
    __syncthreads();

    int cur = 0;
    for (int k0 = 0; k0 < K; k0 += 16) {
        const bool has_next = (k0 + 16 < K);
        if (has_next) {
            const int kn = k0 + 16;
            #pragma unroll
            for (int i = 0; i < 8; i++) {
                int idx = tid + i*256;
                int m = idx >> 4, k = idx & 15;
                ra[i] = A[(long long)(bm+m)*lda + (kn+k)];
            }
            #pragma unroll
            for (int i = 0; i < 4; i++) {
                int idx = tid + i*256;
                if (TRANS_B) { int n = idx >> 4, k = idx & 15; rb[i] = B[(long long)(bn+n)*ldb + (kn+k)]; }
                else         { int k = idx >> 6, n = idx & 63; rb[i] = B[(long long)(kn+k)*ldb + (bn+n)]; }
            }
        }
        #pragma unroll
        for (int kk = 0; kk < 16; kk++) {
            float4 a0 = *(const float4*)&As[cur][kk][ty*8];
            float4 a1 = *(const float4*)&As[cur][kk][ty*8+4];
            float4 b0 = *(const float4*)&Bs[cur][kk][tx*4];
            float af[8] = {a0.x,a0.y,a0.z,a0.w,a1.x,a1.y,a1.z,a1.w};
            float bf[4] = {b0.x,b0.y,b0.z,b0.w};
            #pragma unroll
            for (int i = 0; i < 8; i++)
                #pragma unroll
                for (int j = 0; j < 4; j++)
                    acc[i][j] += af[i]*bf[j];
        }
        if (has_next) {
            const int nxt = cur ^ 1;
            #pragma unroll
            for (int i = 0; i < 8; i++) {
                int idx = tid + i*256;
                int m = idx >> 4, k = idx & 15;
                As[nxt][k][m] = ra[i];
            }
            #pragma unroll
            for (int i = 0; i < 4; i++) {
                int idx = tid + i*256;
                if (TRANS_B) { int n = idx >> 4, k = idx & 15; Bs[nxt][k][n] = rb[i]; }
                else         { int k = idx >> 6, n = idx & 63; Bs[nxt][k][n] = rb[i]; }
            }
            __syncthreads();
            cur = nxt;
        }
    }
    #pragma unroll
    for (int i = 0; i < 8; i++) {
        int row = bm + ty*8 + i;
        float* cp = C + (long long)row*ldc + bn + tx*4;
        #pragma unroll
        for (int j = 0; j < 4; j++) {
            float vv = alpha*acc[i][j];
            if (bi) vv += bi[bn + tx*4 + j];
            cp[j] = vv;
        }
    }
}

// ---------------- fp32 -> bf16 convert (grid-stride) ---------------------------
__global__ void cvt_bf16(const float* __restrict__ src, __nv_bfloat16* __restrict__ dst,
                         long long n)
{
    long long i = (long long)blockIdx.x*blockDim.x + threadIdx.x;
    long long stride = (long long)gridDim.x*blockDim.x;
    for (; i < n; i += stride) dst[i] = __float2bfloat16(src[i]);
}

// ---------------- batched fp32 -> bf16 transpose: dst[z][c][r] = src[z][r][c] --
__global__ void transpose_to_bf16(const float* __restrict__ src,
                                  __nv_bfloat16* __restrict__ dst,
                                  int R, int C, long long sSrc, long long sDst)
{
    __shared__ float tile[32][33];
    src += (long long)blockIdx.z * sSrc;
    dst += (long long)blockIdx.z * sDst;
    int r0 = blockIdx.x*32, c0 = blockIdx.y*32;
    int tx = threadIdx.x, ty = threadIdx.y;       // 32 x 8
    #pragma unroll
    for (int i = 0; i < 4; i++)
        tile[ty + i*8][tx] = src[(long long)(r0 + ty + i*8)*C + c0 + tx];
    __syncthreads();
    #pragma unroll
    for (int i = 0; i < 4; i++)
        dst[(long long)(c0 + ty + i*8)*R + r0 + tx] = __float2bfloat16(tile[tx][ty + i*8]);
}

// ---------------- HMMA bf16 GEMM: C = alpha*(A @ B^T) + bias -------------------
// A: [M, KTOT] bf16 K-major, B: [N, KTOT] bf16 K-major, C: OutT (fp32 or bf16).
// CTA: 256 threads (8 warps, 4x2), tile 128x64; warp tile 32x32 = 2x4 mma tiles.
// bias (fp32, optional): BIAS_ROW ? per-output-row : per-output-column.
template<typename OutT, bool BIAS_ROW>
__global__ void __launch_bounds__(256)
attn_mma(const __nv_bfloat16* __restrict__ A, const __nv_bfloat16* __restrict__ B,
         OutT* __restrict__ C, const float* __restrict__ bias,
         int KTOT, int ldc,
         long long sA, long long sB, long long sC, long long sBias, float alpha)
{
    __shared__ __align__(16) __nv_bfloat16 As[128][72];
    __shared__ __align__(16) __nv_bfloat16 Bs[64][72];

    const int tid = threadIdx.x;
    const int wid = tid >> 5, lane = tid & 31;
    const int wm = wid >> 1, wn = wid & 1;
    const int g = lane >> 2, t = lane & 3;

    const int h = blockIdx.z;
    const __nv_bfloat16* Ag = A + (long long)h*sA + (long long)(blockIdx.y*128)*KTOT;
    const __nv_bfloat16* Bg = B + (long long)h*sB + (long long)(blockIdx.x*64)*KTOT;
    const float* bi = bias ? (bias + (long long)h*sBias) : (const float*)0;

    float acc[2][4][4];
    #pragma unroll
    for (int mi = 0; mi < 2; mi++)
        #pragma unroll
        for (int ni = 0; ni < 4; ni++)
            #pragma unroll
            for (int r = 0; r < 4; r++) acc[mi][ni][r] = 0.0f;

    for (int k0 = 0; k0 < KTOT; k0 += 64) {
        __syncthreads();
        #pragma unroll
        for (int i = 0; i < 4; i++) {
            int idx = tid + i*256;
            int row = idx >> 3, c8 = idx & 7;
            uint4 v = *(const uint4*)(Ag + (long long)row*KTOT + k0 + c8*8);
            *(uint4*)&As[row][c8*8] = v;
        }
        #pragma unroll
        for (int i = 0; i < 2; i++) {
            int idx = tid + i*256;
            int row = idx >> 3, c8 = idx & 7;
            uint4 v = *(const uint4*)(Bg + (long long)row*KTOT + k0 + c8*8);
            *(uint4*)&Bs[row][c8*8] = v;
        }
        __syncthreads();

        #pragma unroll
        for (int ks = 0; ks < 4; ks++) {
            const int kk = ks*16;
            uint32_t a[2][4], b[4][2];
            #pragma unroll
            for (int mi = 0; mi < 2; mi++) {
                int m0 = wm*32 + mi*16;
                a[mi][0] = *(const uint32_t*)&As[m0 + g    ][kk + t*2    ];
                a[mi][1] = *(const uint32_t*)&As[m0 + g + 8][kk + t*2    ];
                a[mi][2] = *(const uint32_t*)&As[m0 + g    ][kk + t*2 + 8];
                a[mi][3] = *(const uint32_t*)&As[m0 + g + 8][kk + t*2 + 8];
            }
            #pragma unroll
            for (int ni = 0; ni < 4; ni++) {
                int n0 = wn*32 + ni*8;
                b[ni][0] = *(const uint32_t*)&Bs[n0 + g][kk + t*2    ];
                b[ni][1] = *(const uint32_t*)&Bs[n0 + g][kk + t*2 + 8];
            }
            #pragma unroll
            for (int mi = 0; mi < 2; mi++)
                #pragma unroll
                for (int ni = 0; ni < 4; ni++)
                    mma16816(acc[mi][ni], a[mi], b[ni]);
        }
    }

    const int base_m = blockIdx.y*128 + wm*32;
    const int base_n = blockIdx.x*64  + wn*32;
    OutT* Cg = C + (long long)h*sC;
    #pragma unroll
    for (int mi = 0; mi < 2; mi++) {
        #pragma unroll
        for (int ni = 0; ni < 4; ni++) {
            int r0 = base_m + mi*16 + g;
            int c0 = base_n + ni*8 + t*2;
            float v0 = alpha*acc[mi][ni][0], v1 = alpha*acc[mi][ni][1];
            float v2 = alpha*acc[mi][ni][2], v3 = alpha*acc[mi][ni][3];
            if (bi) {
                if (BIAS_ROW) {
                    float br0 = bi[r0], br1 = bi[r0 + 8];
                    v0 += br0; v1 += br0; v2 += br1; v3 += br1;
                } else {
                    float bc0 = bi[c0], bc1 = bi[c0 + 1];
                    v0 += bc0; v1 += bc1; v2 += bc0; v3 += bc1;
                }
            }
            store_pair(Cg + (long long)r0*ldc + c0, v0, v1);
            store_pair(Cg + (long long)(r0 + 8)*ldc + c0, v2, v3);
        }
    }
}

// ---------------- row softmax over length-2048 rows ----------------------------
__global__ void softmax2048(float* __restrict__ S)
{
    __shared__ float red[32];
    float* row = S + (long long)blockIdx.x * 2048;
    int tid = threadIdx.x;                         // 256
    float v[8];
    float m = -1e30f;
    #pragma unroll
    for (int i = 0; i < 8; i++) { v[i] = row[tid + i*256]; m = fmaxf(m, v[i]); }
    #pragma unroll
    for (int o = 16; o > 0; o >>= 1) m = fmaxf(m, __shfl_xor_sync(~0u, m, o));
    if ((tid & 31) == 0) red[tid >> 5] = m;
    __syncthreads();
    if (tid == 0) {
        float x = red[0];
        #pragma unroll
        for (int i = 1; i < 8; i++) x = fmaxf(x, red[i]);
        red[0] = x;
    }
    __syncthreads();
    m = red[0];
    __syncthreads();
    float s = 0.0f;
    #pragma unroll
    for (int i = 0; i < 8; i++) { v[i] = __expf(v[i] - m); s += v[i]; }
    #pragma unroll
    for (int o = 16; o > 0; o >>= 1) s += __shfl_xor_sync(~0u, s, o);
    if ((tid & 31) == 0) red[tid >> 5] = s;
    __syncthreads();
    if (tid == 0) {
        float x = 0.0f;
        #pragma unroll
        for (int i = 0; i < 8; i++) x += red[i];
        red[0] = x;
    }
    __syncthreads();
    float inv = 1.0f / red[0];
    #pragma unroll
    for (int i = 0; i < 8; i++) row[tid + i*256] = v[i]*inv;
}

// ---------------- residual + LayerNorm -----------------------------------------
__global__ void resid_ln(const float* __restrict__ gamma, const float* __restrict__ beta)
{
    __shared__ float r1[8], r2[8];
    int s = blockIdx.x, tid = threadIdx.x;         // 256 threads
    const float* xr = g_x   + (long long)s*HDIM;
    const float* mr = g_mha + (long long)s*HDIM;
    float y0 = xr[tid]       + mr[tid];
    float y1 = xr[tid + 256] + mr[tid + 256];
    float sum = y0 + y1, sq = y0*y0 + y1*y1;
    #pragma unroll
    for (int o = 16; o > 0; o >>= 1) {
        sum += __shfl_xor_sync(~0u, sum, o);
        sq  += __shfl_xor_sync(~0u, sq,  o);
    }
    if ((tid & 31) == 0) { r1[tid >> 5] = sum; r2[tid >> 5] = sq; }
    __syncthreads();
    if (tid == 0) {
        float a = 0.0f, b = 0.0f;
        #pragma unroll
        for (int i = 0; i < 8; i++) { a += r1[i]; b += r2[i]; }
        r1[0] = a; r2[0] = b;
    }
    __syncthreads();
    float mu  = r1[0]*(1.0f/512.0f);
    float var = r2[0]*(1.0f/512.0f) - mu*mu;
    float rstd = rsqrtf(var + 1e-5f);
    g_xln[(long long)s*HDIM + tid]       = (y0 - mu)*rstd*gamma[tid]       + beta[tid];
    g_xln[(long long)s*HDIM + 256 + tid] = (y1 - mu)*rstd*gamma[tid + 256] + beta[tid + 256];
}

// ---------------- GRU init: seed h with tag=1, clear stale tags (graph replay!) -
__global__ void gru_init(const float* __restrict__ dec_hid)
{
    int i = threadIdx.x;                           // 512
    g_ht[0][i] = (1ULL << 32) | (unsigned long long)__float_as_uint(dec_hid[i]);
    g_ht[1][i] = 0ULL;                             // stale-tag clear
}

// ---------------- persistent sequential GRU (R6 version: best measured) --------
__global__ void gru_kernel(const float* __restrict__ W_hh,
                           const float* __restrict__ b_hh)
{
    __shared__ float hs[2][HDIM];
    const int tid = threadIdx.x;
    const int warp = tid >> 5, lane = tid & 31;
    const int jj = blockIdx.x * 8 + warp;          // 0..511

    float wr0[16], wr1[16], wr2[16];
    const float* w0 = W_hh + (long long)(jj        )*HDIM + lane;
    const float* w1 = W_hh + (long long)(jj +  512 )*HDIM + lane;
    const float* w2 = W_hh + (long long)(jj + 1024 )*HDIM + lane;
    #pragma unroll
    for (int i = 0; i < 16; i++) { wr0[i] = w0[32*i]; wr1[i] = w1[32*i]; wr2[i] = w2[32*i]; }
    const float bh0 = b_hh[jj], bh1 = b_hh[jj + 512], bh2 = b_hh[jj + 1024];

    for (int t = 0; t < SEQ; t++) {
        float gr = __ldcg(&g_gi[(long long)t*G3 + jj]);
        float gz = __ldcg(&g_gi[(long long)t*G3 + jj + 512]);
        float gn = __ldcg(&g_gi[(long long)t*G3 + jj + 1024]);

        const unsigned long long* hb = g_ht[t & 1];
        const unsigned expect = (unsigned)(t + 1);
        unsigned long long v0 = ld_acq_u64(&hb[tid]);
        unsigned long long v1 = ld_acq_u64(&hb[tid + 256]);
        while ((unsigned)(v0 >> 32) != expect) v0 = ld_acq_u64(&hb[tid]);
        while ((unsigned)(v1 >> 32) != expect) v1 = ld_acq_u64(&hb[tid + 256]);

        float* hcur = hs[t & 1];
        hcur[tid]       = __uint_as_float((unsigned)v0);
        hcur[tid + 256] = __uint_as_float((unsigned)v1);
        __syncthreads();

        float hprev = hcur[jj];
        float a0 = 0.0f, a1 = 0.0f, a2 = 0.0f;
        #pragma unroll
        for (int i = 0; i < 16; i++) {
            float h = hcur[lane + 32*i];
            a0 += h*wr0[i];
            a1 += h*wr1[i];
            a2 += h*wr2[i];
        }
        #pragma unroll
        for (int o = 16; o > 0; o >>= 1) {
            a0 += __shfl_xor_sync(~0u, a0, o);
            a1 += __shfl_xor_sync(~0u, a1, o);
            a2 += __shfl_xor_sync(~0u, a2, o);
        }

        if (lane == 0) {
            float r = 0.5f + 0.5f*tanh_fast(0.5f*(gr + a0 + bh0));
            float z = 0.5f + 0.5f*tanh_fast(0.5f*(gz + a1 + bh1));
            float n = tanh_fast(gn + r*(a2 + bh2));
            float hnew = fmaf(z, hprev - n, n);    // (1-z)*n + z*h
            unsigned long long w = ((unsigned long long)(unsigned)(t + 2) << 32)
                                 | (unsigned long long)__float_as_uint(hnew);
            st_rel_u64(&g_ht[(t + 1) & 1][jj], w);
        }
        // no trailing barrier: hs double-buffered; overwrite gated by tag chain.
    }
}

// ---------------- final projection: logits = h @ W_out + b_out -----------------
__global__ void logits_kernel(const float* __restrict__ W_out,
                              const float* __restrict__ b_out)
{
    __shared__ float hsm[HDIM];
    for (int i = threadIdx.x; i < HDIM; i += 256)
        hsm[i] = __uint_as_float((unsigned)g_ht[0][i]);
    __syncthreads();
    int v = blockIdx.x*256 + threadIdx.x;
    if (v >= VOCAB) return;
    float acc = b_out[v];
    #pragma unroll 4
    for (int d = 0; d < HDIM; d++) acc += hsm[d]*W_out[(long long)d*VOCAB + v];
    g_logits[v] = acc;
}

__global__ void lse_kernel()
{
    __shared__ float red[32];
    int tid = threadIdx.x;                         // 1024
    float m = -1e30f;
    for (int i = tid; i < VOCAB; i += 1024) m = fmaxf(m, g_logits[i]);
    #pragma unroll
    for (int o = 16; o > 0; o >>= 1) m = fmaxf(m, __shfl_xor_sync(~0u, m, o));
    if ((tid & 31) == 0) red[tid >> 5] = m;
    __syncthreads();
    if (tid == 0) {
        float x = red[0];
        #pragma unroll
        for (int i = 1; i < 32; i++) x = fmaxf(x, red[i]);
        red[0] = x;
    }
    __syncthreads();
    m = red[0];
    __syncthreads();
    float s = 0.0f;
    for (int i = tid; i < VOCAB; i += 1024) s += expf(g_logits[i] - m);
    #pragma unroll
    for (int o = 16; o > 0; o >>= 1) s += __shfl_xor_sync(~0u, s, o);
    if ((tid & 31) == 0) red[tid >> 5] = s;
    __syncthreads();
    if (tid == 0) {
        float x = 0.0f;
        #pragma unroll
        for (int i = 0; i < 32; i++) x += red[i];
        g_lse = m + logf(x);
    }
}

__global__ void out_kernel(float* __restrict__ out)
{
    int i = blockIdx.x*256 + threadIdx.x;
    if (i < VOCAB)            out[i] = g_logits[i] - g_lse;
    else if (i < VOCAB+HDIM)  out[i] = __uint_as_float((unsigned)g_ht[0][i - VOCAB]);
}

// ================================ host side =====================================
extern "C" void kernel_launch(void* const* d_in, const int* in_sizes, int n_in,
                              void* d_out, int out_size)
{
    const int*   tok     = (const int*)  d_in[0];
    const float* dec_hid = (const float*)d_in[1];
    const float* emb     = (const float*)d_in[2];
    const float* Wq      = (const float*)d_in[3];
    const float* bq      = (const float*)d_in[4];
    const float* Wk      = (const float*)d_in[5];
    const float* bk      = (const float*)d_in[6];
    const float* Wv      = (const float*)d_in[7];
    const float* bv      = (const float*)d_in[8];
    const float* Wo      = (const float*)d_in[9];
    const float* bo      = (const float*)d_in[10];
    const float* gamma   = (const float*)d_in[11];
    const float* beta    = (const float*)d_in[12];
    const float* W_ih    = (const float*)d_in[13];
    const float* W_hh    = (const float*)d_in[14];
    const float* b_ih    = (const float*)d_in[15];
    const float* b_hh    = (const float*)d_in[16];
    const float* W_out   = (const float*)d_in[17];
    const float* b_out   = (const float*)d_in[18];
    float* out = (float*)d_out;

    float *psc, *pmha, *pxln, *pgi;
    cudaGetSymbolAddress((void**)&psc,  g_sc);
    cudaGetSymbolAddress((void**)&pmha, g_mha);
    cudaGetSymbolAddress((void**)&pxln, g_xln);
    cudaGetSymbolAddress((void**)&pgi,  g_gi);
    __nv_bfloat16 *pxb, *pwqt, *pwkt, *pwvt, *pwot, *pqb, *pkb, *pvtb, *ppb, *pcatb;
    cudaGetSymbolAddress((void**)&pxb,   g_xb);
    cudaGetSymbolAddress((void**)&pwqt,  g_wqt);
    cudaGetSymbolAddress((void**)&pwkt,  g_wkt);
    cudaGetSymbolAddress((void**)&pwvt,  g_wvt);
    cudaGetSymbolAddress((void**)&pwot,  g_wot);
    cudaGetSymbolAddress((void**)&pqb,   g_qb);
    cudaGetSymbolAddress((void**)&pkb,   g_kb);
    cudaGetSymbolAddress((void**)&pvtb,  g_vtb);
    cudaGetSymbolAddress((void**)&ppb,   g_pb);
    cudaGetSymbolAddress((void**)&pcatb, g_catb);

    const long long HH = (long long)HDIM*HDIM;

    // 1) embedding gather (fp32 + bf16)
    embed_kernel<<<SEQ, 128>>>(tok, emb);

    // 2) weight transposes -> bf16 (Wq/Wk/Wv per head: [d][e] -> [e][d]; Wo: [k][n] -> [n][k])
    transpose_to_bf16<<<dim3(16,16,NH), dim3(32,8)>>>(Wq, pwqt, HDIM, HDIM, HH, HH);
    transpose_to_bf16<<<dim3(16,16,NH), dim3(32,8)>>>(Wk, pwkt, HDIM, HDIM, HH, HH);
    transpose_to_bf16<<<dim3(16,16,NH), dim3(32,8)>>>(Wv, pwvt, HDIM, HDIM, HH, HH);
    transpose_to_bf16<<<dim3(96,16,1),  dim3(32,8)>>>(Wo, pwot, NH*HDIM, HDIM,
                                                      0LL, 0LL);

    // 3) Q = x@Wq + bq (bf16 out), K likewise — HMMA
    attn_mma<__nv_bfloat16,false><<<dim3(HDIM/64, SEQ/128, NH), 256>>>(
        pxb, pwqt, pqb, bq, HDIM, HDIM,
        0LL, HH, (long long)SEQ*HDIM, (long long)HDIM, 1.0f);
    attn_mma<__nv_bfloat16,false><<<dim3(HDIM/64, SEQ/128, NH), 256>>>(
        pxb, pwkt, pkb, bk, HDIM, HDIM,
        0LL, HH, (long long)SEQ*HDIM, (long long)HDIM, 1.0f);

    // 4) V^T directly: vtb[e][t] = sum_d WvT[e][d]*x[t][d] + bv[e] (row bias)
    attn_mma<__nv_bfloat16,true><<<dim3(SEQ/64, HDIM/128, NH), 256>>>(
        pwvt, pxb, pvtb, bv, HDIM, SEQ,
        HH, 0LL, (long long)HDIM*SEQ, (long long)HDIM, 1.0f);

    // 5) scores = Q @ K^T / sqrt(H) (fp32 out)
    attn_mma<float,false><<<dim3(SEQ/64, SEQ/128, NH), 256>>>(
        pqb, pkb, psc, (const float*)0, HDIM, SEQ,
        (long long)SEQ*HDIM, (long long)SEQ*HDIM, (long long)SEQ*SEQ, 0LL,
        0.04419417382415922f);

    // 6) softmax over last dim
    softmax2048<<<NH*SEQ, 256>>>(psc);

    // 7) P -> bf16
    cvt_bf16<<<8192, 256>>>(psc, ppb, (long long)NH*SEQ*SEQ);

    // 8) heads = P @ V (B = V^T), bf16 out straight into concat layout
    attn_mma<__nv_bfloat16,false><<<dim3(HDIM/64, SEQ/128, NH), 256>>>(
        ppb, pvtb, pcatb, (const float*)0, SEQ, NH*HDIM,
        (long long)SEQ*SEQ, (long long)HDIM*SEQ, (long long)HDIM, 0LL, 1.0f);

    // 9) mha = cat @ Wo + bo (fp32 out)
    attn_mma<float,false><<<dim3(HDIM/64, SEQ/128, 1), 256>>>(
        pcatb, pwot, pmha, bo, NH*HDIM, HDIM,
        0LL, 0LL, 0LL, 0LL, 1.0f);

    // 10) residual + layernorm
    resid_ln<<<SEQ, 256>>>(gamma, beta);

    // 11) gi = xln @ W_ih^T + b_ih (fp32 — GRU precision containment)
    gemm128<true><<<dim3(24,16,1), 256>>>(pxln, W_ih, b_ih, pgi,
        SEQ, G3, HDIM, HDIM, HDIM, G3, 0LL, 0LL, 0LL, 0LL, 1.0f);

    // 12) sequential GRU (R6 best configuration)
    gru_init<<<1, 512>>>(dec_hid);
    gru_kernel<<<GRU_NCTA, 256>>>(W_hh, b_hh);

    // 13) logits + log_softmax + outputs
    logits_kernel<<<(VOCAB+255)/256, 256>>>(W_out, b_out);
    lse_kernel<<<1, 1024>>>();
    out_kernel<<<(VOCAB+HDIM+255)/256, 256>>>(out);
}

// round 16
// speedup vs baseline: 1.6645x; 1.0116x over previous
#include <cuda_runtime.h>
#include <cuda_bf16.h>
#include <math.h>
#include <stdint.h>

#define SEQ   2048
#define HDIM  512
#define NH    6
#define VOCAB 32000
#define G3    1536          // 3*HDIM
#define GRU_NCTA 64         // 64 CTAs x 256 threads (best measured shape)

// ---------------- scratch (device globals; no allocations allowed) -------------
__device__ float g_x   [SEQ*HDIM];                 // embeddings (fp32, residual path)
__device__ float g_sc  [(size_t)NH*SEQ*SEQ];       // attention scores (fp32)
__device__ float g_mha [SEQ*HDIM];
__device__ float g_xln [SEQ*HDIM];                 // post-LN sequence (GRU input, fp32)
__device__ float g_gi  [SEQ*G3];                   // xln @ W_ih^T + b_ih (fp32)
__device__ unsigned long long g_ht[2][HDIM];       // tagged hidden: (tag<<32)|f32bits
__device__ float g_logits[VOCAB];
__device__ float g_lse;
// bf16 operands
__device__ __nv_bfloat16 g_xb  [SEQ*HDIM];         // x bf16
__device__ __nv_bfloat16 g_wqt [NH*HDIM*HDIM];     // Wq^T per head [h][e][d]
__device__ __nv_bfloat16 g_wkt [NH*HDIM*HDIM];
__device__ __nv_bfloat16 g_wvt [NH*HDIM*HDIM];
__device__ __nv_bfloat16 g_wot [HDIM*NH*HDIM];     // Wo^T [n=512][k=3072]
__device__ __nv_bfloat16 g_qb  [NH*SEQ*HDIM];      // Q bf16 [h][s][e]
__device__ __nv_bfloat16 g_kb  [NH*SEQ*HDIM];      // K bf16 [h][s][e]
__device__ __nv_bfloat16 g_vtb [NH*HDIM*SEQ];      // V^T bf16 [h][e][t]
__device__ __nv_bfloat16 g_pb  [(size_t)NH*SEQ*SEQ];// P bf16 [h][s][t]
__device__ __nv_bfloat16 g_catb[SEQ*NH*HDIM];      // concat heads bf16 [s][h*512+e]

// STRONG (morally strong -> single-copy atomic per PTX model) 64-bit ops.
__device__ __forceinline__ unsigned long long ld_acq_u64(const unsigned long long* p){
    unsigned long long v;
    asm volatile("ld.acquire.gpu.global.u64 %0, [%1];" : "=l"(v) : "l"(p) : "memory");
    return v;
}
__device__ __forceinline__ void st_rel_u64(unsigned long long* p, unsigned long long v){
    asm volatile("st.release.gpu.global.u64 [%0], %1;" :: "l"(p), "l"(v) : "memory");
}
__device__ __forceinline__ float tanh_fast(float x){
    float y; asm("tanh.approx.f32 %0, %1;" : "=f"(y) : "f"(x)); return y;
}

// ---------------- mma.sync m16n8k16 bf16 (baseline PTX; HMMA on sm_103) --------
__device__ __forceinline__ void mma16816(float* c, const uint32_t* a, const uint32_t* b){
    asm volatile(
      "mma.sync.aligned.m16n8k16.row.col.f32.bf16.bf16.f32 "
      "{%0,%1,%2,%3}, {%4,%5,%6,%7}, {%8,%9}, {%0,%1,%2,%3};"
      : "+f"(c[0]), "+f"(c[1]), "+f"(c[2]), "+f"(c[3])
      : "r"(a[0]), "r"(a[1]), "r"(a[2]), "r"(a[3]), "r"(b[0]), "r"(b[1]));
}
__device__ __forceinline__ void store_pair(float* p, float a, float b){
    *(float2*)p = make_float2(a, b);
}
__device__ __forceinline__ void store_pair(__nv_bfloat16* p, float a, float b){
    *(__nv_bfloat162*)p = __floats2bfloat162_rn(a, b);
}

// ---------------- embedding gather ---------------------------------------------
__global__ void embed_kernel(const int* __restrict__ tok,
                             const float* __restrict__ emb)
{
    int s = blockIdx.x;
    long long t = tok[s];
    const float4* src = (const float4*)(emb + t*HDIM);
    float4* dst = (float4*)(g_x + (long long)s*HDIM);
    int i = threadIdx.x;               // 128 threads
    float4 v = src[i];
    dst[i] = v;
    __nv_bfloat16* db = g_xb + (long long)s*HDIM + i*4;
    db[0] = __float2bfloat16(v.x); db[1] = __float2bfloat16(v.y);
    db[2] = __float2bfloat16(v.z); db[3] = __float2bfloat16(v.w);
}

// ---------------- fp32 tiled GEMM (R6; used for gi only — GRU needs fp32) ------
template<bool TRANS_B>
__global__ void __launch_bounds__(256, 2)
gemm128(const float* __restrict__ A, const float* __restrict__ B,
        const float* __restrict__ bias, float* __restrict__ C,
        int M, int N, int K, int lda, int ldb, int ldc,
        long long sA, long long sB, long long sC, long long sBias,
        float alpha)
{
    __shared__ float As[2][16][132];
    __shared__ float Bs[2][16][68];
    A += (long long)blockIdx.z * sA;
    B += (long long)blockIdx.z * sB;
    C += (long long)blockIdx.z * sC;
    const float* bi = bias ? (bias + (long long)blockIdx.z * sBias) : (const float*)0;

    const int bm = blockIdx.y * 128;
    const int bn = blockIdx.x * 64;
    const int tid = threadIdx.x;
    const int tx = tid & 15, ty = tid >> 4;

    float acc[8][4];
    #pragma unroll
    for (int i = 0; i < 8; i++)
        #pragma unroll
        for (int j = 0; j < 4; j++) acc[i][j] = 0.0f;

    float ra[8], rb[4];

    #pragma unroll
    for (int i = 0; i < 8; i++) {
        int idx = tid + i*256;
        int m = idx >> 4, k = idx & 15;
        ra[i] = A[(long long)(bm+m)*lda + k];
    }
    #pragma unroll
    for (int i = 0; i < 4; i++) {
        int idx = tid + i*256;
        if (TRANS_B) { int n = idx >> 4, k = idx & 15; rb[i] = B[(long long)(bn+n)*ldb + k]; }
        else         { int k = idx >> 6, n = idx & 63; rb[i] = B[(long long)k*ldb + (bn+n)]; }
    }
    #pragma unroll
    for (int i = 0; i < 8; i++) {
        int idx = tid + i*256;
        int m = idx >> 4, k = idx & 15;
        As[0][k][m] = ra[i];
    }
    #pragma unroll
    for (int i = 0; i < 4; i++) {
        int idx = tid + i*256;
        if (TRANS_B) { int n = idx >> 4, k = idx & 15; Bs[0][k][n] = rb[i]; }
        else         { int k = idx >> 6, n = idx & 63; Bs[0][k][n] = rb[i]; }
    }
    __syncthreads();

    int cur = 0;
    for (int k0 = 0; k0 < K; k0 += 16) {
        const bool has_next = (k0 + 16 < K);
        if (has_next) {
            const int kn = k0 + 16;
            #pragma unroll
            for (int i = 0; i < 8; i++) {
                int idx = tid + i*256;
                int m = idx >> 4, k = idx & 15;
                ra[i] = A[(long long)(bm+m)*lda + (kn+k)];
            }
            #pragma unroll
            for (int i = 0; i < 4; i++) {
                int idx = tid + i*256;
                if (TRANS_B) { int n = idx >> 4, k = idx & 15; rb[i] = B[(long long)(bn+n)*ldb + (kn+k)]; }
                else         { int k = idx >> 6, n = idx & 63; rb[i] = B[(long long)(kn+k)*ldb + (bn+n)]; }
            }
        }
        #pragma unroll
        for (int kk = 0; kk < 16; kk++) {
            float4 a0 = *(const float4*)&As[cur][kk][ty*8];
            float4 a1 = *(const float4*)&As[cur][kk][ty*8+4];
            float4 b0 = *(const float4*)&Bs[cur][kk][tx*4];
            float af[8] = {a0.x,a0.y,a0.z,a0.w,a1.x,a1.y,a1.z,a1.w};
            float bf[4] = {b0.x,b0.y,b0.z,b0.w};
            #pragma unroll
            for (int i = 0; i < 8; i++)
                #pragma unroll
                for (int j = 0; j < 4; j++)
                    acc[i][j] += af[i]*bf[j];
        }
        if (has_next) {
            const int nxt = cur ^ 1;
            #pragma unroll
            for (int i = 0; i < 8; i++) {
                int idx = tid + i*256;
                int m = idx >> 4, k = idx & 15;
                As[nxt][k][m] = ra[i];
            }
            #pragma unroll
            for (int i = 0; i < 4; i++) {
                int idx = tid + i*256;
                if (TRANS_B) { int n = idx >> 4, k = idx & 15; Bs[nxt][k][n] = rb[i]; }
                else         { int k = idx >> 6, n = idx & 63; Bs[nxt][k][n] = rb[i]; }
            }
            __syncthreads();
            cur = nxt;
        }
    }
    #pragma unroll
    for (int i = 0; i < 8; i++) {
        int row = bm + ty*8 + i;
        float* cp = C + (long long)row*ldc + bn + tx*4;
        #pragma unroll
        for (int j = 0; j < 4; j++) {
            float vv = alpha*acc[i][j];
            if (bi) vv += bi[bn + tx*4 + j];
            cp[j] = vv;
        }
    }
}

// ---------------- batched fp32 -> bf16 transpose: dst[z][c][r] = src[z][r][c] --
__global__ void transpose_to_bf16(const float* __restrict__ src,
                                  __nv_bfloat16* __restrict__ dst,
                                  int R, int C, long long sSrc, long long sDst)
{
    __shared__ float tile[32][33];
    src += (long long)blockIdx.z * sSrc;
    dst += (long long)blockIdx.z * sDst;
    int r0 = blockIdx.x*32, c0 = blockIdx.y*32;
    int tx = threadIdx.x, ty = threadIdx.y;       // 32 x 8
    #pragma unroll
    for (int i = 0; i < 4; i++)
        tile[ty + i*8][tx] = src[(long long)(r0 + ty + i*8)*C + c0 + tx];
    __syncthreads();
    #pragma unroll
    for (int i = 0; i < 4; i++)
        dst[(long long)(c0 + ty + i*8)*R + r0 + tx] = __float2bfloat16(tile[tx][ty + i*8]);
}

// ---------------- HMMA bf16 GEMM: C = alpha*(A @ B^T) + bias -------------------
// A: [M, KTOT] bf16 K-major, B: [N, KTOT] bf16 K-major, C: OutT (fp32 or bf16).
// CTA: 256 threads (8 warps, 4x2), tile 128x64; warp tile 32x32 = 2x4 mma tiles.
// DOUBLE-BUFFERED smem: LDG of chunk k+1 overlaps HMMA of chunk k; ONE barrier
// per chunk. bias (fp32, optional): BIAS_ROW ? per-output-row : per-column.
#define ATTN_SMEM_ELEMS (2*128*72 + 2*64*72)
#define ATTN_SMEM_BYTES (ATTN_SMEM_ELEMS*2)
template<typename OutT, bool BIAS_ROW>
__global__ void __launch_bounds__(256)
attn_mma(const __nv_bfloat16* __restrict__ A, const __nv_bfloat16* __restrict__ B,
         OutT* __restrict__ C, const float* __restrict__ bias,
         int KTOT, int ldc,
         long long sA, long long sB, long long sC, long long sBias, float alpha)
{
    extern __shared__ __nv_bfloat16 smem_db[];
    __nv_bfloat16 (*As)[128][72] = (__nv_bfloat16(*)[128][72])smem_db;
    __nv_bfloat16 (*Bs)[64][72]  = (__nv_bfloat16(*)[64][72])(smem_db + 2*128*72);

    const int tid = threadIdx.x;
    const int wid = tid >> 5, lane = tid & 31;
    const int wm = wid >> 1, wn = wid & 1;
    const int g = lane >> 2, t = lane & 3;

    const int h = blockIdx.z;
    const __nv_bfloat16* Ag = A + (long long)h*sA + (long long)(blockIdx.y*128)*KTOT;
    const __nv_bfloat16* Bg = B + (long long)h*sB + (long long)(blockIdx.x*64)*KTOT;
    const float* bi = bias ? (bias + (long long)h*sBias) : (const float*)0;

    const int rowA = tid >> 3, c8 = tid & 7;      // per-thread tile coords
    const int rowA2 = rowA + 32, rowA3 = rowA + 64, rowA4 = rowA + 96;
    const int rowB = rowA, rowB2 = rowA2;         // B uses first 2 slices

    float acc[2][4][4];
    #pragma unroll
    for (int mi = 0; mi < 2; mi++)
        #pragma unroll
        for (int ni = 0; ni < 4; ni++)
            #pragma unroll
            for (int r = 0; r < 4; r++) acc[mi][ni][r] = 0.0f;

    // prologue: chunk 0 -> buffer 0
    {
        *(uint4*)&As[0][rowA ][c8*8] = *(const uint4*)(Ag + (long long)rowA *KTOT + c8*8);
        *(uint4*)&As[0][rowA2][c8*8] = *(const uint4*)(Ag + (long long)rowA2*KTOT + c8*8);
        *(uint4*)&As[0][rowA3][c8*8] = *(const uint4*)(Ag + (long long)rowA3*KTOT + c8*8);
        *(uint4*)&As[0][rowA4][c8*8] = *(const uint4*)(Ag + (long long)rowA4*KTOT + c8*8);
        *(uint4*)&Bs[0][rowB ][c8*8] = *(const uint4*)(Bg + (long long)rowB *KTOT + c8*8);
        *(uint4*)&Bs[0][rowB2][c8*8] = *(const uint4*)(Bg + (long long)rowB2*KTOT + c8*8);
    }
    __syncthreads();

    int cur = 0;
    for (int k0 = 0; k0 < KTOT; k0 += 64) {
        const bool has_next = (k0 + 64 < KTOT);
        uint4 ra0, ra1, ra2, ra3, rb0, rb1;
        if (has_next) {
            const int kn = k0 + 64;
            ra0 = *(const uint4*)(Ag + (long long)rowA *KTOT + kn + c8*8);
            ra1 = *(const uint4*)(Ag + (long long)rowA2*KTOT + kn + c8*8);
            ra2 = *(const uint4*)(Ag + (long long)rowA3*KTOT + kn + c8*8);
            ra3 = *(const uint4*)(Ag + (long long)rowA4*KTOT + kn + c8*8);
            rb0 = *(const uint4*)(Bg + (long long)rowB *KTOT + kn + c8*8);
            rb1 = *(const uint4*)(Bg + (long long)rowB2*KTOT + kn + c8*8);
        }
        // compute on buffer cur (overlaps with the LDGs above)
        #pragma unroll
        for (int ks = 0; ks < 4; ks++) {
            const int kk = ks*16;
            uint32_t a[2][4], b[4][2];
            #pragma unroll
            for (int mi = 0; mi < 2; mi++) {
                int m0 = wm*32 + mi*16;
                a[mi][0] = *(const uint32_t*)&As[cur][m0 + g    ][kk + t*2    ];
                a[mi][1] = *(const uint32_t*)&As[cur][m0 + g + 8][kk + t*2    ];
                a[mi][2] = *(const uint32_t*)&As[cur][m0 + g    ][kk + t*2 + 8];
                a[mi][3] = *(const uint32_t*)&As[cur][m0 + g + 8][kk + t*2 + 8];
            }
            #pragma unroll
            for (int ni = 0; ni < 4; ni++) {
                int n0 = wn*32 + ni*8;
                b[ni][0] = *(const uint32_t*)&Bs[cur][n0 + g][kk + t*2    ];
                b[ni][1] = *(const uint32_t*)&Bs[cur][n0 + g][kk + t*2 + 8];
            }
            #pragma unroll
            for (int mi = 0; mi < 2; mi++)
                #pragma unroll
                for (int ni = 0; ni < 4; ni++)
                    mma16816(acc[mi][ni], a[mi], b[ni]);
        }
        if (has_next) {
            const int nxt = cur ^ 1;
            *(uint4*)&As[nxt][rowA ][c8*8] = ra0;
            *(uint4*)&As[nxt][rowA2][c8*8] = ra1;
            *(uint4*)&As[nxt][rowA3][c8*8] = ra2;
            *(uint4*)&As[nxt][rowA4][c8*8] = ra3;
            *(uint4*)&Bs[nxt][rowB ][c8*8] = rb0;
            *(uint4*)&Bs[nxt][rowB2][c8*8] = rb1;
            __syncthreads();
            cur = nxt;
        }
    }

    const int base_m = blockIdx.y*128 + wm*32;
    const int base_n = blockIdx.x*64  + wn*32;
    OutT* Cg = C + (long long)h*sC;
    #pragma unroll
    for (int mi = 0; mi < 2; mi++) {
        #pragma unroll
        for (int ni = 0; ni < 4; ni++) {
            int r0 = base_m + mi*16 + g;
            int c0 = base_n + ni*8 + t*2;
            float v0 = alpha*acc[mi][ni][0], v1 = alpha*acc[mi][ni][1];
            float v2 = alpha*acc[mi][ni][2], v3 = alpha*acc[mi][ni][3];
            if (bi) {
                if (BIAS_ROW) {
                    float br0 = bi[r0], br1 = bi[r0 + 8];
                    v0 += br0; v1 += br0; v2 += br1; v3 += br1;
                } else {
                    float bc0 = bi[c0], bc1 = bi[c0 + 1];
                    v0 += bc0; v1 += bc1; v2 += bc0; v3 += bc1;
                }
            }
            store_pair(Cg + (long long)r0*ldc + c0, v0, v1);
            store_pair(Cg + (long long)(r0 + 8)*ldc + c0, v2, v3);
        }
    }
}

// ---------------- row softmax over length-2048 rows, bf16 output ---------------
__global__ void softmax2048(const float* __restrict__ S, __nv_bfloat16* __restrict__ P)
{
    __shared__ float red[32];
    const float* row = S + (long long)blockIdx.x * 2048;
    __nv_bfloat16* prow = P + (long long)blockIdx.x * 2048;
    int tid = threadIdx.x;                         // 256
    float v[8];
    float m = -1e30f;
    #pragma unroll
    for (int i = 0; i < 8; i++) { v[i] = row[tid + i*256]; m = fmaxf(m, v[i]); }
    #pragma unroll
    for (int o = 16; o > 0; o >>= 1) m = fmaxf(m, __shfl_xor_sync(~0u, m, o));
    if ((tid & 31) == 0) red[tid >> 5] = m;
    __syncthreads();
    if (tid == 0) {
        float x = red[0];
        #pragma unroll
        for (int i = 1; i < 8; i++) x = fmaxf(x, red[i]);
        red[0] = x;
    }
    __syncthreads();
    m = red[0];
    __syncthreads();
    float s = 0.0f;
    #pragma unroll
    for (int i = 0; i < 8; i++) { v[i] = __expf(v[i] - m); s += v[i]; }
    #pragma unroll
    for (int o = 16; o > 0; o >>= 1) s += __shfl_xor_sync(~0u, s, o);
    if ((tid & 31) == 0) red[tid >> 5] = s;
    __syncthreads();
    if (tid == 0) {
        float x = 0.0f;
        #pragma unroll
        for (int i = 0; i < 8; i++) x += red[i];
        red[0] = x;
    }
    __syncthreads();
    float inv = 1.0f / red[0];
    #pragma unroll
    for (int i = 0; i < 8; i++) prow[tid + i*256] = __float2bfloat16(v[i]*inv);
}

// ---------------- residual + LayerNorm (fp32 out — GRU precision) --------------
__global__ void resid_ln(const float* __restrict__ gamma, const float* __restrict__ beta)
{
    __shared__ float r1[8], r2[8];
    int s = blockIdx.x, tid = threadIdx.x;         // 256 threads
    const float* xr = g_x   + (long long)s*HDIM;
    const float* mr = g_mha + (long long)s*HDIM;
    float y0 = xr[tid]       + mr[tid];
    float y1 = xr[tid + 256] + mr[tid + 256];
    float sum = y0 + y1, sq = y0*y0 + y1*y1;
    #pragma unroll
    for (int o = 16; o > 0; o >>= 1) {
        sum += __shfl_xor_sync(~0u, sum, o);
        sq  += __shfl_xor_sync(~0u, sq,  o);
    }
    if ((tid & 31) == 0) { r1[tid >> 5] = sum; r2[tid >> 5] = sq; }
    __syncthreads();
    if (tid == 0) {
        float a = 0.0f, b = 0.0f;
        #pragma unroll
        for (int i = 0; i < 8; i++) { a += r1[i]; b += r2[i]; }
        r1[0] = a; r2[0] = b;
    }
    __syncthreads();
    float mu  = r1[0]*(1.0f/512.0f);
    float var = r2[0]*(1.0f/512.0f) - mu*mu;
    float rstd = rsqrtf(var + 1e-5f);
    g_xln[(long long)s*HDIM + tid]       = (y0 - mu)*rstd*gamma[tid]       + beta[tid];
    g_xln[(long long)s*HDIM + 256 + tid] = (y1 - mu)*rstd*gamma[tid + 256] + beta[tid + 256];
}

// ---------------- GRU init: seed h with tag=1, clear stale tags (graph replay!) -
__global__ void gru_init(const float* __restrict__ dec_hid)
{
    int i = threadIdx.x;                           // 512
    g_ht[0][i] = (1ULL << 32) | (unsigned long long)__float_as_uint(dec_hid[i]);
    g_ht[1][i] = 0ULL;                             // stale-tag clear
}

// ---------------- persistent sequential GRU (R6 version: best measured) --------
__global__ void gru_kernel(const float* __restrict__ W_hh,
                           const float* __restrict__ b_hh)
{
    __shared__ float hs[2][HDIM];
    const int tid = threadIdx.x;
    const int warp = tid >> 5, lane = tid & 31;
    const int jj = blockIdx.x * 8 + warp;          // 0..511

    float wr0[16], wr1[16], wr2[16];
    const float* w0 = W_hh + (long long)(jj        )*HDIM + lane;
    const float* w1 = W_hh + (long long)(jj +  512 )*HDIM + lane;
    const float* w2 = W_hh + (long long)(jj + 1024 )*HDIM + lane;
    #pragma unroll
    for (int i = 0; i < 16; i++) { wr0[i] = w0[32*i]; wr1[i] = w1[32*i]; wr2[i] = w2[32*i]; }
    const float bh0 = b_hh[jj], bh1 = b_hh[jj + 512], bh2 = b_hh[jj + 1024];

    for (int t = 0; t < SEQ; t++) {
        float gr = __ldcg(&g_gi[(long long)t*G3 + jj]);
        float gz = __ldcg(&g_gi[(long long)t*G3 + jj + 512]);
        float gn = __ldcg(&g_gi[(long long)t*G3 + jj + 1024]);

        const unsigned long long* hb = g_ht[t & 1];
        const unsigned expect = (unsigned)(t + 1);
        unsigned long long v0 = ld_acq_u64(&hb[tid]);
        unsigned long long v1 = ld_acq_u64(&hb[tid + 256]);
        while ((unsigned)(v0 >> 32) != expect) v0 = ld_acq_u64(&hb[tid]);
        while ((unsigned)(v1 >> 32) != expect) v1 = ld_acq_u64(&hb[tid + 256]);

        float* hcur = hs[t & 1];
        hcur[tid]       = __uint_as_float((unsigned)v0);
        hcur[tid + 256] = __uint_as_float((unsigned)v1);
        __syncthreads();

        float hprev = hcur[jj];
        float a0 = 0.0f, a1 = 0.0f, a2 = 0.0f;
        #pragma unroll
        for (int i = 0; i < 16; i++) {
            float h = hcur[lane + 32*i];
            a0 += h*wr0[i];
            a1 += h*wr1[i];
            a2 += h*wr2[i];
        }
        #pragma unroll
        for (int o = 16; o > 0; o >>= 1) {
            a0 += __shfl_xor_sync(~0u, a0, o);
            a1 += __shfl_xor_sync(~0u, a1, o);
            a2 += __shfl_xor_sync(~0u, a2, o);
        }

        if (lane == 0) {
            float r = 0.5f + 0.5f*tanh_fast(0.5f*(gr + a0 + bh0));
            float z = 0.5f + 0.5f*tanh_fast(0.5f*(gz + a1 + bh1));
            float n = tanh_fast(gn + r*(a2 + bh2));
            float hnew = fmaf(z, hprev - n, n);    // (1-z)*n + z*h
            unsigned long long w = ((unsigned long long)(unsigned)(t + 2) << 32)
                                 | (unsigned long long)__float_as_uint(hnew);
            st_rel_u64(&g_ht[(t + 1) & 1][jj], w);
        }
        // no trailing barrier: hs double-buffered; overwrite gated by tag chain.
    }
}

// ---------------- final projection: logits = h @ W_out + b_out -----------------
__global__ void logits_kernel(const float* __restrict__ W_out,
                              const float* __restrict__ b_out)
{
    __shared__ float hsm[HDIM];
    for (int i = threadIdx.x; i < HDIM; i += 256)
        hsm[i] = __uint_as_float((unsigned)g_ht[0][i]);
    __syncthreads();
    int v = blockIdx.x*256 + threadIdx.x;
    if (v >= VOCAB) return;
    float acc = b_out[v];
    #pragma unroll 4
    for (int d = 0; d < HDIM; d++) acc += hsm[d]*W_out[(long long)d*VOCAB + v];
    g_logits[v] = acc;
}

__global__ void lse_kernel()
{
    __shared__ float red[32];
    int tid = threadIdx.x;                         // 1024
    float m = -1e30f;
    for (int i = tid; i < VOCAB; i += 1024) m = fmaxf(m, g_logits[i]);
    #pragma unroll
    for (int o = 16; o > 0; o >>= 1) m = fmaxf(m, __shfl_xor_sync(~0u, m, o));
    if ((tid & 31) == 0) red[tid >> 5] = m;
    __syncthreads();
    if (tid == 0) {
        float x = red[0];
        #pragma unroll
        for (int i = 1; i < 32; i++) x = fmaxf(x, red[i]);
        red[0] = x;
    }
    __syncthreads();
    m = red[0];
    __syncthreads();
    float s = 0.0f;
    for (int i = tid; i < VOCAB; i += 1024) s += expf(g_logits[i] - m);
    #pragma unroll
    for (int o = 16; o > 0; o >>= 1) s += __shfl_xor_sync(~0u, s, o);
    if ((tid & 31) == 0) red[tid >> 5] = s;
    __syncthreads();
    if (tid == 0) {
        float x = 0.0f;
        #pragma unroll
        for (int i = 0; i < 32; i++) x += red[i];
        g_lse = m + logf(x);
    }
}

__global__ void out_kernel(float* __restrict__ out)
{
    int i = blockIdx.x*256 + threadIdx.x;
    if (i < VOCAB)            out[i] = g_logits[i] - g_lse;
    else if (i < VOCAB+HDIM)  out[i] = __uint_as_float((unsigned)g_ht[0][i - VOCAB]);
}

// ================================ host side =====================================
extern "C" void kernel_launch(void* const* d_in, const int* in_sizes, int n_in,
                              void* d_out, int out_size)
{
    const int*   tok     = (const int*)  d_in[0];
    const float* dec_hid = (const float*)d_in[1];
    const float* emb     = (const float*)d_in[2];
    const float* Wq      = (const float*)d_in[3];
    const float* bq      = (const float*)d_in[4];
    const float* Wk      = (const float*)d_in[5];
    const float* bk      = (const float*)d_in[6];
    const float* Wv      = (const float*)d_in[7];
    const float* bv      = (const float*)d_in[8];
    const float* Wo      = (const float*)d_in[9];
    const float* bo      = (const float*)d_in[10];
    const float* gamma   = (const float*)d_in[11];
    const float* beta    = (const float*)d_in[12];
    const float* W_ih    = (const float*)d_in[13];
    const float* W_hh    = (const float*)d_in[14];
    const float* b_ih    = (const float*)d_in[15];
    const float* b_hh    = (const float*)d_in[16];
    const float* W_out   = (const float*)d_in[17];
    const float* b_out   = (const float*)d_in[18];
    float* out = (float*)d_out;

    float *psc, *pmha, *pxln, *pgi;
    cudaGetSymbolAddress((void**)&psc,  g_sc);
    cudaGetSymbolAddress((void**)&pmha, g_mha);
    cudaGetSymbolAddress((void**)&pxln, g_xln);
    cudaGetSymbolAddress((void**)&pgi,  g_gi);
    __nv_bfloat16 *pxb, *pwqt, *pwkt, *pwvt, *pwot;
    __nv_bfloat16 *pqb, *pkb, *pvtb, *ppb, *pcatb;
    cudaGetSymbolAddress((void**)&pxb,   g_xb);
    cudaGetSymbolAddress((void**)&pwqt,  g_wqt);
    cudaGetSymbolAddress((void**)&pwkt,  g_wkt);
    cudaGetSymbolAddress((void**)&pwvt,  g_wvt);
    cudaGetSymbolAddress((void**)&pwot,  g_wot);
    cudaGetSymbolAddress((void**)&pqb,   g_qb);
    cudaGetSymbolAddress((void**)&pkb,   g_kb);
    cudaGetSymbolAddress((void**)&pvtb,  g_vtb);
    cudaGetSymbolAddress((void**)&ppb,   g_pb);
    cudaGetSymbolAddress((void**)&pcatb, g_catb);

    const long long HH = (long long)HDIM*HDIM;

    // raise dynamic smem limit for the double-buffered HMMA kernels
    cudaFuncSetAttribute(attn_mma<float,false>,
        cudaFuncAttributeMaxDynamicSharedMemorySize, ATTN_SMEM_BYTES);
    cudaFuncSetAttribute(attn_mma<__nv_bfloat16,false>,
        cudaFuncAttributeMaxDynamicSharedMemorySize, ATTN_SMEM_BYTES);
    cudaFuncSetAttribute(attn_mma<__nv_bfloat16,true>,
        cudaFuncAttributeMaxDynamicSharedMemorySize, ATTN_SMEM_BYTES);

    // 1) embedding gather (fp32 + bf16)
    embed_kernel<<<SEQ, 128>>>(tok, emb);

    // 2) weight transposes -> bf16
    transpose_to_bf16<<<dim3(16,16,NH), dim3(32,8)>>>(Wq, pwqt, HDIM, HDIM, HH, HH);
    transpose_to_bf16<<<dim3(16,16,NH), dim3(32,8)>>>(Wk, pwkt, HDIM, HDIM, HH, HH);
    transpose_to_bf16<<<dim3(16,16,NH), dim3(32,8)>>>(Wv, pwvt, HDIM, HDIM, HH, HH);
    transpose_to_bf16<<<dim3(96,16,1),  dim3(32,8)>>>(Wo, pwot, NH*HDIM, HDIM, 0LL, 0LL);

    // 3) Q = x@Wq + bq (bf16 out), K likewise — HMMA
    attn_mma<__nv_bfloat16,false><<<dim3(HDIM/64, SEQ/128, NH), 256, ATTN_SMEM_BYTES>>>(
        pxb, pwqt, pqb, bq, HDIM, HDIM,
        0LL, HH, (long long)SEQ*HDIM, (long long)HDIM, 1.0f);
    attn_mma<__nv_bfloat16,false><<<dim3(HDIM/64, SEQ/128, NH), 256, ATTN_SMEM_BYTES>>>(
        pxb, pwkt, pkb, bk, HDIM, HDIM,
        0LL, HH, (long long)SEQ*HDIM, (long long)HDIM, 1.0f);

    // 4) V^T directly: vtb[e][t] = sum_d WvT[e][d]*x[t][d] + bv[e] (row bias)
    attn_mma<__nv_bfloat16,true><<<dim3(SEQ/64, HDIM/128, NH), 256, ATTN_SMEM_BYTES>>>(
        pwvt, pxb, pvtb, bv, HDIM, SEQ,
        HH, 0LL, (long long)HDIM*SEQ, (long long)HDIM, 1.0f);

    // 5) scores = Q @ K^T / sqrt(H) (fp32 out)
    attn_mma<float,false><<<dim3(SEQ/64, SEQ/128, NH), 256, ATTN_SMEM_BYTES>>>(
        pqb, pkb, psc, (const float*)0, HDIM, SEQ,
        (long long)SEQ*HDIM, (long long)SEQ*HDIM, (long long)SEQ*SEQ, 0LL,
        0.04419417382415922f);

    // 6) softmax over last dim -> bf16 P directly
    softmax2048<<<NH*SEQ, 256>>>(psc, ppb);

    // 7) heads = P @ V (B = V^T), bf16 out straight into concat layout
    attn_mma<__nv_bfloat16,false><<<dim3(HDIM/64, SEQ/128, NH), 256, ATTN_SMEM_BYTES>>>(
        ppb, pvtb, pcatb, (const float*)0, SEQ, NH*HDIM,
        (long long)SEQ*SEQ, (long long)HDIM*SEQ, (long long)HDIM, 0LL, 1.0f);

    // 8) mha = cat @ Wo + bo (fp32 out)
    attn_mma<float,false><<<dim3(HDIM/64, SEQ/128, 1), 256, ATTN_SMEM_BYTES>>>(
        pcatb, pwot, pmha, bo, NH*HDIM, HDIM,
        0LL, 0LL, 0LL, 0LL, 1.0f);

    // 9) residual + layernorm (fp32 out — GRU path stays fp32)
    resid_ln<<<SEQ, 256>>>(gamma, beta);

    // 10) gi = xln @ W_ih^T + b_ih — fp32 gemm128 (output 1 = raw h demands it)
    gemm128<true><<<dim3(24,16,1), 256>>>(pxln, W_ih, b_ih, pgi,
        SEQ, G3, HDIM, HDIM, HDIM, G3, 0LL, 0LL, 0LL, 0LL, 1.0f);

    // 11) sequential GRU (R6 best configuration)
    gru_init<<<1, 512>>>(dec_hid);
    gru_kernel<<<GRU_NCTA, 256>>>(W_hh, b_hh);

    // 12) logits + log_softmax + outputs
    logits_kernel<<<(VOCAB+255)/256, 256>>>(W_out, b_out);
    lse_kernel<<<1, 1024>>>();
    out_kernel<<<(VOCAB+HDIM+255)/256, 256>>>(out);
}